// round 2
// baseline (speedup 1.0000x reference)
#include <cuda_runtime.h>
#include <cuda_bf16.h>
#include <cstdint>

// Problem constants
#define BATCH   4
#define TFRAMES 32
#define NPTS    4096
#define FOUT    16       // output frames
#define GROUPS  64       // BATCH * FOUT
#define MANCH   128      // anchors per group (N / 32)
#define KNBR    32       // neighbors
#define C0      64
#define C1      128

// Scratch: displacement float4 (dx,dy,dz,dt) per (dt, group, anchor, k)
__device__ float4 g_disp[3 * GROUPS * MANCH * KNBR];   // 12.58 MB

// ---------------------------------------------------------------------------
// packed f32x2 FMA (Blackwell)
// ---------------------------------------------------------------------------
__device__ __forceinline__ unsigned long long fma2(unsigned long long a,
                                                   unsigned long long b,
                                                   unsigned long long c) {
    unsigned long long d;
    asm("fma.rn.f32x2 %0, %1, %2, %3;" : "=l"(d) : "l"(a), "l"(b), "l"(c));
    return d;
}

// ---------------------------------------------------------------------------
// Kernel 1: furthest point sampling. One block per group. 512 threads,
// 8 points per thread held in registers. Writes anchor xyz directly into the
// new_xyzs section of d_out (also consumed by the ball-query kernel).
// ---------------------------------------------------------------------------
__global__ __launch_bounds__(512) void fps_kernel(const float* __restrict__ xyzs,
                                                  float* __restrict__ out_xyz) {
    const int g = blockIdx.x;
    const int b = g >> 4, f = g & 15;
    const float* fr = xyzs + ((size_t)(b * TFRAMES + 2 * f) * NPTS) * 3;
    const int tid = threadIdx.x;

    float px[8], py[8], pz[8], dist[8];
#pragma unroll
    for (int j = 0; j < 8; ++j) {
        int p = j * 512 + tid;
        px[j] = fr[p * 3 + 0];
        py[j] = fr[p * 3 + 1];
        pz[j] = fr[p * 3 + 2];
        dist[j] = 1e10f;
    }

    __shared__ float cx, cy, cz;
    __shared__ float swv[16];
    __shared__ int   swi[16];

    if (tid == 0) {
        float x = fr[0], y = fr[1], z = fr[2];
        cx = x; cy = y; cz = z;
        float* o = out_xyz + (size_t)g * MANCH * 3;
        o[0] = x; o[1] = y; o[2] = z;
    }
    __syncthreads();

    for (int s = 1; s < MANCH; ++s) {
        const float lx = cx, ly = cy, lz = cz;
        float bv = -1.0f;
        int   bi = 0;
#pragma unroll
        for (int j = 0; j < 8; ++j) {
            float dx = px[j] - lx;
            float dy = py[j] - ly;
            float dz = pz[j] - lz;
            float d = __fadd_rn(__fadd_rn(__fmul_rn(dx, dx), __fmul_rn(dy, dy)),
                                __fmul_rn(dz, dz));
            float nd = fminf(dist[j], d);
            dist[j] = nd;
            if (nd > bv) { bv = nd; bi = j * 512 + tid; }
        }
        // warp argmax (lowest index on tie)
#pragma unroll
        for (int off = 16; off; off >>= 1) {
            float ov = __shfl_down_sync(0xffffffffu, bv, off);
            int   oi = __shfl_down_sync(0xffffffffu, bi, off);
            if (ov > bv || (ov == bv && oi < bi)) { bv = ov; bi = oi; }
        }
        if ((tid & 31) == 0) { swv[tid >> 5] = bv; swi[tid >> 5] = bi; }
        __syncthreads();
        if (tid < 32) {
            bv = (tid < 16) ? swv[tid] : -2.0f;
            bi = (tid < 16) ? swi[tid] : 0x7fffffff;
#pragma unroll
            for (int off = 8; off; off >>= 1) {
                float ov = __shfl_down_sync(0xffffffffu, bv, off);
                int   oi = __shfl_down_sync(0xffffffffu, bi, off);
                if (ov > bv || (ov == bv && oi < bi)) { bv = ov; bi = oi; }
            }
            if (tid == 0) {
                float x = fr[bi * 3 + 0], y = fr[bi * 3 + 1], z = fr[bi * 3 + 2];
                cx = x; cy = y; cz = z;
                float* o = out_xyz + ((size_t)g * MANCH + s) * 3;
                o[0] = x; o[1] = y; o[2] = z;
            }
        }
        __syncthreads();
    }
}

// ---------------------------------------------------------------------------
// Kernel 2: ball query (first 32 indices with d2 < r^2, in index order;
// unfilled slots replicated with first valid, or index 0). Writes the
// displacement float4 directly. One block per (group, dt); frame in smem.
// ---------------------------------------------------------------------------
__global__ __launch_bounds__(256) void ball_kernel(const float* __restrict__ xyzs,
                                                   const float* __restrict__ anchors) {
    const int bid = blockIdx.x;          // 0..191
    const int g = bid / 3, dti = bid % 3;
    const int dt = dti - 1;
    const int b = g >> 4, f = g & 15;
    int t = 2 * f + dt;
    t = min(max(t, 0), TFRAMES - 1);
    const float* fr = xyzs + (size_t)(b * TFRAMES + t) * NPTS * 3;

    __shared__ float sp[NPTS * 3];       // 48 KB
    for (int i = threadIdx.x; i < NPTS * 3; i += 256) sp[i] = fr[i];
    __syncthreads();

    const int w = threadIdx.x >> 5;
    const int lane = threadIdx.x & 31;
    const float r2 = (float)(0.15 * 0.15);
    const float tch = (float)dt;

    for (int m = w; m < MANCH; m += 8) {
        const float* a = anchors + ((size_t)g * MANCH + m) * 3;
        const float ax = a[0], ay = a[1], az = a[2];
        float4* od = g_disp + ((size_t)(dti * GROUPS + g) * MANCH + m) * KNBR;

        int filled = 0;
        float fx = 0.f, fy = 0.f, fz = 0.f;
        bool havefirst = false;

        for (int base = 0; base < NPTS; base += 32) {
            const int j = base + lane;
            float dx = sp[j * 3 + 0] - ax;
            float dy = sp[j * 3 + 1] - ay;
            float dz = sp[j * 3 + 2] - az;
            float d2 = __fadd_rn(__fadd_rn(__fmul_rn(dx, dx), __fmul_rn(dy, dy)),
                                 __fmul_rn(dz, dz));
            bool pred = d2 < r2;
            unsigned mask = __ballot_sync(0xffffffffu, pred);
            if (mask) {
                int pos = filled + __popc(mask & ((1u << lane) - 1u));
                if (pred && pos < KNBR) od[pos] = make_float4(dx, dy, dz, tch);
                if (!havefirst) {
                    int src = __ffs(mask) - 1;
                    fx = __shfl_sync(0xffffffffu, dx, src);
                    fy = __shfl_sync(0xffffffffu, dy, src);
                    fz = __shfl_sync(0xffffffffu, dz, src);
                    havefirst = true;
                }
                filled += __popc(mask);
                if (filled >= KNBR) break;
            }
        }
        if (filled < KNBR) {
            if (!havefirst) {   // no point in radius -> index 0
                fx = sp[0] - ax; fy = sp[1] - ay; fz = sp[2] - az;
            }
            int s = filled + lane;
            if (s < KNBR) od[s] = make_float4(fx, fy, fz, tch);
        }
    }
}

// ---------------------------------------------------------------------------
// Kernel 3: two-layer MLP + max over k + sum over dt.
// One block handles 8 anchors of one group. 128 threads: thread o owns output
// channel o (Wm row packed into 32 x 64-bit regs for f32x2 FMAs).
// ---------------------------------------------------------------------------
#define ANCH 8
__global__ __launch_bounds__(128) void mlp_kernel(const float* __restrict__ Wd,
                                                  const float* __restrict__ Wm,
                                                  float* __restrict__ out) {
    const int blk = blockIdx.x;            // 1024 blocks
    const int g = blk >> 4;
    const int m0 = (blk & 15) * ANCH;
    const int o = threadIdx.x;

    __shared__ float  wd[C0 * 4];          // 1 KB
    __shared__ float4 d4[KNBR];            // 512 B
    __shared__ float  hsh[KNBR * C0];      // 8 KB

    wd[o]       = Wd[o];
    wd[o + 128] = Wd[o + 128];

    unsigned long long wm[32];
    {
        const unsigned long long* wmg = (const unsigned long long*)(Wm + (size_t)o * C0);
#pragma unroll
        for (int i = 0; i < 32; ++i) wm[i] = wmg[i];
    }
    __syncthreads();

    for (int a = 0; a < ANCH; ++a) {
        float fsum = 0.f;
        for (int dti = 0; dti < 3; ++dti) {
            if (o < KNBR)
                d4[o] = g_disp[((size_t)(dti * GROUPS + g) * MANCH + (m0 + a)) * KNBR + o];
            __syncthreads();

            // layer 1: h[k][c] = relu(d4[k] . Wd[c])
#pragma unroll
            for (int r = 0; r < 16; ++r) {
                int idx = r * 128 + o;       // == k*64 + c
                int k = idx >> 6, c = idx & 63;
                float4 dv = d4[k];
                const float* w = &wd[c * 4];
                float v = w[0] * dv.x + w[1] * dv.y + w[2] * dv.z + w[3] * dv.w;
                hsh[idx] = fmaxf(v, 0.f);
            }
            __syncthreads();

            // layer 2: thread o computes max_k relu(h[k] . Wm[o]) via f32x2
            float vmax = -1e30f;
            for (int k = 0; k < KNBR; k += 2) {
                unsigned long long a0 = 0ull, a1 = 0ull;
                const ulonglong2* h0 = (const ulonglong2*)(hsh + k * C0);
                const ulonglong2* h1 = (const ulonglong2*)(hsh + (k + 1) * C0);
#pragma unroll
                for (int it = 0; it < 16; ++it) {
                    ulonglong2 v0 = h0[it];
                    ulonglong2 v1 = h1[it];
                    a0 = fma2(v0.x, wm[2 * it],     a0);
                    a0 = fma2(v0.y, wm[2 * it + 1], a0);
                    a1 = fma2(v1.x, wm[2 * it],     a1);
                    a1 = fma2(v1.y, wm[2 * it + 1], a1);
                }
                float2 f0 = *(float2*)&a0;
                float2 f1 = *(float2*)&a1;
                vmax = fmaxf(vmax, f0.x + f0.y);
                vmax = fmaxf(vmax, f1.x + f1.y);
            }
            fsum += fmaxf(vmax, 0.f);
            __syncthreads();   // protect hsh/d4 before next dt
        }
        // new_features[b, f, o, m] at offset 24576 + (g*128 + o)*128 + m
        out[24576 + ((size_t)g * C1 + o) * MANCH + (m0 + a)] = fsum;
    }
}

// ---------------------------------------------------------------------------
extern "C" void kernel_launch(void* const* d_in, const int* in_sizes, int n_in,
                              void* d_out, int out_size) {
    const float* xyzs = (const float*)d_in[0];
    const float* Wd   = (const float*)d_in[1];
    const float* Wm   = (const float*)d_in[2];
    float* out = (float*)d_out;

    fps_kernel<<<GROUPS, 512>>>(xyzs, out);
    ball_kernel<<<GROUPS * 3, 256>>>(xyzs, out);
    mlp_kernel<<<GROUPS * (MANCH / ANCH), 128>>>(Wd, Wm, out);
}

// round 4
// speedup vs baseline: 1.7780x; 1.7780x over previous
#include <cuda_runtime.h>
#include <cuda_bf16.h>
#include <cstdint>

#define BATCH   4
#define TFRAMES 32
#define NPTS    4096
#define FOUT    16
#define GROUPS  64
#define MANCH   128
#define KNBR    32
#define C0      64
#define C1      128

__device__ float4 g_disp[3 * GROUPS * MANCH * KNBR];   // 12.58 MB scratch

// ---------------------------------------------------------------------------
// Kernel 1: FPS. 256 threads, 16 pts/thread in registers, frame mirrored in
// smem, one barrier/iter via packed 64-bit smem atomicMax (distbits || ~idx).
// ---------------------------------------------------------------------------
__global__ __launch_bounds__(256) void fps_kernel(const float* __restrict__ xyzs,
                                                  float* __restrict__ out_xyz) {
    const int g = blockIdx.x;
    const int b = g >> 4, f = g & 15;
    const float* fr = xyzs + ((size_t)(b * TFRAMES + 2 * f) * NPTS) * 3;
    const int tid = threadIdx.x;

    __shared__ float sp[NPTS * 3];                 // 48 KB
    __shared__ unsigned long long best[3];
    for (int i = tid; i < NPTS * 3; i += 256) sp[i] = fr[i];
    if (tid < 3) best[tid] = 0ull;
    __syncthreads();

    float px[16], py[16], pz[16], dist[16];
#pragma unroll
    for (int j = 0; j < 16; ++j) {
        int p = j * 256 + tid;
        px[j] = sp[p * 3 + 0];
        py[j] = sp[p * 3 + 1];
        pz[j] = sp[p * 3 + 2];
        dist[j] = 1e10f;
    }

    float cx = sp[0], cy = sp[1], cz = sp[2];
    if (tid == 0) {
        float* o = out_xyz + (size_t)g * MANCH * 3;
        o[0] = cx; o[1] = cy; o[2] = cz;
    }

    for (int s = 1; s < MANCH; ++s) {
        float bv = -1.0f;
        int   bj = 0;
#pragma unroll
        for (int j = 0; j < 16; ++j) {
            float dx = px[j] - cx;
            float dy = py[j] - cy;
            float dz = pz[j] - cz;
            float d = __fadd_rn(__fadd_rn(__fmul_rn(dx, dx), __fmul_rn(dy, dy)),
                                __fmul_rn(dz, dz));
            float nd = fminf(dist[j], d);
            dist[j] = nd;
            if (nd > bv) { bv = nd; bj = j; }
        }
        int bi = bj * 256 + tid;
#pragma unroll
        for (int off = 16; off; off >>= 1) {
            float ov = __shfl_down_sync(0xffffffffu, bv, off);
            int   oi = __shfl_down_sync(0xffffffffu, bi, off);
            if (ov > bv || (ov == bv && oi < bi)) { bv = ov; bi = oi; }
        }
        const int slot = s % 3;
        if ((tid & 31) == 0) {
            unsigned long long key =
                ((unsigned long long)__float_as_uint(bv) << 32) | (unsigned)(~bi);
            atomicMax(&best[slot], key);
        }
        __syncthreads();
        unsigned long long k = best[slot];
        int wi = (int)(~(unsigned)k);
        cx = sp[wi * 3 + 0]; cy = sp[wi * 3 + 1]; cz = sp[wi * 3 + 2];
        if (tid == 0) {
            best[(s + 2) % 3] = 0ull;              // reset 2 iters ahead (barrier-ordered)
            float* o = out_xyz + ((size_t)g * MANCH + s) * 3;
            o[0] = cx; o[1] = cy; o[2] = cz;
        }
    }
}

// ---------------------------------------------------------------------------
// Kernel 2: ball query -> displacement float4 (unchanged; passed R2)
// ---------------------------------------------------------------------------
__global__ __launch_bounds__(256) void ball_kernel(const float* __restrict__ xyzs,
                                                   const float* __restrict__ anchors) {
    const int bid = blockIdx.x;
    const int g = bid / 3, dti = bid % 3;
    const int dt = dti - 1;
    const int b = g >> 4, f = g & 15;
    int t = 2 * f + dt;
    t = min(max(t, 0), TFRAMES - 1);
    const float* fr = xyzs + (size_t)(b * TFRAMES + t) * NPTS * 3;

    __shared__ float sp[NPTS * 3];
    for (int i = threadIdx.x; i < NPTS * 3; i += 256) sp[i] = fr[i];
    __syncthreads();

    const int w = threadIdx.x >> 5;
    const int lane = threadIdx.x & 31;
    const float r2 = (float)(0.15 * 0.15);
    const float tch = (float)dt;

    for (int m = w; m < MANCH; m += 8) {
        const float* a = anchors + ((size_t)g * MANCH + m) * 3;
        const float ax = a[0], ay = a[1], az = a[2];
        float4* od = g_disp + ((size_t)(dti * GROUPS + g) * MANCH + m) * KNBR;

        int filled = 0;
        float fx = 0.f, fy = 0.f, fz = 0.f;
        bool havefirst = false;

        for (int base = 0; base < NPTS; base += 32) {
            const int j = base + lane;
            float dx = sp[j * 3 + 0] - ax;
            float dy = sp[j * 3 + 1] - ay;
            float dz = sp[j * 3 + 2] - az;
            float d2 = __fadd_rn(__fadd_rn(__fmul_rn(dx, dx), __fmul_rn(dy, dy)),
                                 __fmul_rn(dz, dz));
            bool pred = d2 < r2;
            unsigned mask = __ballot_sync(0xffffffffu, pred);
            if (mask) {
                int pos = filled + __popc(mask & ((1u << lane) - 1u));
                if (pred && pos < KNBR) od[pos] = make_float4(dx, dy, dz, tch);
                if (!havefirst) {
                    int src = __ffs(mask) - 1;
                    fx = __shfl_sync(0xffffffffu, dx, src);
                    fy = __shfl_sync(0xffffffffu, dy, src);
                    fz = __shfl_sync(0xffffffffu, dz, src);
                    havefirst = true;
                }
                filled += __popc(mask);
                if (filled >= KNBR) break;
            }
        }
        if (filled < KNBR) {
            if (!havefirst) {
                fx = sp[0] - ax; fy = sp[1] - ay; fz = sp[2] - az;
            }
            int s = filled + lane;
            if (s < KNBR) od[s] = make_float4(fx, fy, fz, tch);
        }
    }
}

// ---------------------------------------------------------------------------
// Kernel 3: MLP via mma.sync m16n8k16 bf16 (3-pass split for fp32 accuracy).
// Block = 128 threads (4 warps). Block handles one group-eighth (16 anchors).
// Per iteration: 2 anchors x 1 dt. D[o(128,M), k(2x32,N)] over K=64 channels.
// Warp w owns output rows [32w, 32w+32) (2 M-tiles); Wm split frags in regs.
// ---------------------------------------------------------------------------
#define HBW 36    // smem words per h-row (64 bf16 = 32 words + 4 pad, conflict-free B loads)

__device__ __forceinline__ void split2(float v0, float v1, uint32_t& hi, uint32_t& lo) {
    __nv_bfloat162 h2 = __floats2bfloat162_rn(v0, v1);   // .x = v0 (low)
    hi = *(uint32_t*)&h2;
    float h0f = __uint_as_float(hi << 16);
    float h1f = __uint_as_float(hi & 0xffff0000u);
    __nv_bfloat162 l2 = __floats2bfloat162_rn(v0 - h0f, v1 - h1f);
    lo = *(uint32_t*)&l2;
}

#define MMA_BF16(d, a, b0, b1)                                                  \
    asm("mma.sync.aligned.m16n8k16.row.col.f32.bf16.bf16.f32 "                  \
        "{%0,%1,%2,%3}, {%4,%5,%6,%7}, {%8,%9}, {%0,%1,%2,%3};"                 \
        : "+f"((d)[0]), "+f"((d)[1]), "+f"((d)[2]), "+f"((d)[3])                \
        : "r"((a)[0]), "r"((a)[1]), "r"((a)[2]), "r"((a)[3]), "r"(b0), "r"(b1))

__global__ __launch_bounds__(128, 1) void mlp_kernel(const float* __restrict__ Wd,
                                                     const float* __restrict__ Wm,
                                                     float* __restrict__ out) {
    __shared__ float4   s_wd[C0];              // 1 KB
    __shared__ uint32_t s_hb[2][64 * HBW];     // 18 KB  (hi/lo bf16x2, row = a*32+k)
    __shared__ float    s_obuf[C1 * 16];       // 8 KB

    const int tid = threadIdx.x;
    const int w = tid >> 5, lane = tid & 31;
    const int q = lane & 3, nl = lane >> 2;
    const int g = blockIdx.x >> 3;
    const int m_base = (blockIdx.x & 7) * 16;

    if (tid < C0) s_wd[tid] = ((const float4*)Wd)[tid];

    // Wm split fragments in registers: Ahi/Alo[mt][kt][j]
    uint32_t Ahi[2][4][4], Alo[2][4][4];
#pragma unroll
    for (int rr = 0; rr < 4; ++rr) {
        const int r = 32 * w + 16 * (rr >> 1) + 8 * (rr & 1) + nl;
        const float* wr = Wm + (size_t)r * C0;
#pragma unroll
        for (int kt = 0; kt < 4; ++kt)
#pragma unroll
            for (int hf = 0; hf < 2; ++hf) {
                float2 v = *(const float2*)(wr + kt * 16 + 8 * hf + 2 * q);
                split2(v.x, v.y, Ahi[rr >> 1][kt][(rr & 1) + 2 * hf],
                                 Alo[rr >> 1][kt][(rr & 1) + 2 * hf]);
            }
    }
    __syncthreads();

    // layer-1 mapping: thread -> (anchor-in-pair, k, c-half)
    const int l1_a  = tid >> 6;
    const int l1_k  = (tid >> 1) & 31;
    const int l1_ch = tid & 1;
    uint32_t* hrow_hi = &s_hb[0][(l1_a * 32 + l1_k) * HBW + l1_ch * 16];
    uint32_t* hrow_lo = &s_hb[1][(l1_a * 32 + l1_k) * HBW + l1_ch * 16];
    const float4* wd_half = s_wd + l1_ch * 32;

    float fsum[2][2][2];                       // [mt][rowhalf][anchor]
#pragma unroll
    for (int i = 0; i < 8; ++i) (&fsum[0][0][0])[i] = 0.f;

    for (int pair = 0; pair < 8; ++pair) {
        for (int dti = 0; dti < 3; ++dti) {
            // ---- layer 1: h -> bf16 hi/lo in smem ----
            const int m = m_base + pair * 2 + l1_a;
            float4 dv = g_disp[((size_t)(dti * GROUPS + g) * MANCH + m) * KNBR + l1_k];
#pragma unroll
            for (int j = 0; j < 16; ++j) {
                float4 w0 = wd_half[2 * j], w1 = wd_half[2 * j + 1];
                float h0 = fmaxf(fmaf(w0.w, dv.w, fmaf(w0.z, dv.z,
                                 fmaf(w0.y, dv.y, w0.x * dv.x))), 0.f);
                float h1 = fmaxf(fmaf(w1.w, dv.w, fmaf(w1.z, dv.z,
                                 fmaf(w1.y, dv.y, w1.x * dv.x))), 0.f);
                split2(h0, h1, hrow_hi[j], hrow_lo[j]);
            }
            __syncthreads();

            // ---- tensor: D += Wm_split . h_split^T ----
            float acc[2][8][4];
#pragma unroll
            for (int i = 0; i < 64; ++i) (&acc[0][0][0])[i] = 0.f;
#pragma unroll
            for (int nt = 0; nt < 8; ++nt) {
                const uint32_t* chi = &s_hb[0][(nt * 8 + nl) * HBW];
                const uint32_t* clo = &s_hb[1][(nt * 8 + nl) * HBW];
#pragma unroll
                for (int kt = 0; kt < 4; ++kt) {
                    uint32_t bh0 = chi[kt * 8 + q];
                    uint32_t bh1 = chi[kt * 8 + q + 4];
                    uint32_t bl0 = clo[kt * 8 + q];
                    uint32_t bl1 = clo[kt * 8 + q + 4];
#pragma unroll
                    for (int mt = 0; mt < 2; ++mt) {
                        MMA_BF16(acc[mt][nt], Ahi[mt][kt], bh0, bh1);
                        MMA_BF16(acc[mt][nt], Ahi[mt][kt], bl0, bl1);
                        MMA_BF16(acc[mt][nt], Alo[mt][kt], bh0, bh1);
                    }
                }
            }
            __syncthreads();   // hb consumed; next iter may overwrite

            // ---- epilogue: max over k (tile cols + quad shuffle), relu, sum ----
#pragma unroll
            for (int mt = 0; mt < 2; ++mt)
#pragma unroll
                for (int a = 0; a < 2; ++a) {
                    float m0 = -1e30f, m1 = -1e30f;
#pragma unroll
                    for (int nt = a * 4; nt < a * 4 + 4; ++nt) {
                        m0 = fmaxf(m0, fmaxf(acc[mt][nt][0], acc[mt][nt][1]));
                        m1 = fmaxf(m1, fmaxf(acc[mt][nt][2], acc[mt][nt][3]));
                    }
                    m0 = fmaxf(m0, __shfl_xor_sync(0xffffffffu, m0, 1));
                    m0 = fmaxf(m0, __shfl_xor_sync(0xffffffffu, m0, 2));
                    m1 = fmaxf(m1, __shfl_xor_sync(0xffffffffu, m1, 1));
                    m1 = fmaxf(m1, __shfl_xor_sync(0xffffffffu, m1, 2));
                    fsum[mt][0][a] += fmaxf(m0, 0.f);
                    fsum[mt][1][a] += fmaxf(m1, 0.f);
                }
        }
        // stage this anchor-pair's results
        if (q == 0) {
#pragma unroll
            for (int mt = 0; mt < 2; ++mt)
#pragma unroll
                for (int rh = 0; rh < 2; ++rh)
#pragma unroll
                    for (int a = 0; a < 2; ++a) {
                        int o = 32 * w + 16 * mt + 8 * rh + nl;
                        s_obuf[o * 16 + pair * 2 + a] = fsum[mt][rh][a];
                    }
        }
#pragma unroll
        for (int i = 0; i < 8; ++i) (&fsum[0][0][0])[i] = 0.f;
    }
    __syncthreads();

    // coalesced-ish final store: thread = output channel
    float4* dst = (float4*)(out + 24576 + ((size_t)g * C1 + tid) * MANCH + m_base);
    const float4* src = (const float4*)(s_obuf + tid * 16);
#pragma unroll
    for (int i = 0; i < 4; ++i) dst[i] = src[i];
}

// ---------------------------------------------------------------------------
extern "C" void kernel_launch(void* const* d_in, const int* in_sizes, int n_in,
                              void* d_out, int out_size) {
    const float* xyzs = (const float*)d_in[0];
    const float* Wd   = (const float*)d_in[1];
    const float* Wm   = (const float*)d_in[2];
    float* out = (float*)d_out;

    fps_kernel<<<GROUPS, 256>>>(xyzs, out);
    ball_kernel<<<GROUPS * 3, 256>>>(xyzs, out);
    mlp_kernel<<<GROUPS * 8, 128>>>(Wd, Wm, out);
}

// round 5
// speedup vs baseline: 1.8300x; 1.0292x over previous
#include <cuda_runtime.h>
#include <cuda_bf16.h>
#include <cstdint>

#define BATCH   4
#define TFRAMES 32
#define NPTS    4096
#define FOUT    16
#define GROUPS  64
#define MANCH   128
#define KNBR    32
#define C0      64
#define C1      128

__device__ float4 g_disp[3 * GROUPS * MANCH * KNBR];   // 12.58 MB scratch

typedef unsigned long long ull;

// ---- packed f32x2 helpers (fma.rn.f32x2 proven on this harness in R2) ----
__device__ __forceinline__ ull fma2(ull a, ull b, ull c) {
    ull d;
    asm("fma.rn.f32x2 %0, %1, %2, %3;" : "=l"(d) : "l"(a), "l"(b), "l"(c));
    return d;
}
__device__ __forceinline__ ull packf(float lo, float hi) {
    ull r;
    asm("mov.b64 %0, {%1, %2};" : "=l"(r) : "f"(lo), "f"(hi));
    return r;
}
__device__ __forceinline__ void unpackf(ull v, float& lo, float& hi) {
    asm("mov.b64 {%0, %1}, %2;" : "=f"(lo), "=f"(hi) : "l"(v));
}

// ---------------------------------------------------------------------------
// Kernel 1: FPS. 256 threads, 16 pts/thread (8 f32x2 pairs) in registers.
// Per iter: packed-exact dist update, redux argmax (exact first-max index),
// 8 smem keys, ONE barrier, no atomics.
// ---------------------------------------------------------------------------
__global__ __launch_bounds__(256) void fps_kernel(const float* __restrict__ xyzs,
                                                  float* __restrict__ out_xyz) {
    const int g = blockIdx.x;
    const int b = g >> 4, f = g & 15;
    const float* fr = xyzs + ((size_t)(b * TFRAMES + 2 * f) * NPTS) * 3;
    const int tid = threadIdx.x;
    const int wid = tid >> 5, lane = tid & 31;

    __shared__ float sp[NPTS * 3];                 // 48 KB
    __shared__ ull wkey[2][8];
    for (int i = tid; i < NPTS * 3; i += 256) sp[i] = fr[i];
    __syncthreads();

    const ull ONE2 = packf(1.0f, 1.0f);
    ull px2[8], py2[8], pz2[8];
    float dist[16];
#pragma unroll
    for (int j = 0; j < 8; ++j) {
        int p0 = j * 512 + tid, p1 = p0 + 256;
        px2[j] = packf(sp[p0 * 3 + 0], sp[p1 * 3 + 0]);
        py2[j] = packf(sp[p0 * 3 + 1], sp[p1 * 3 + 1]);
        pz2[j] = packf(sp[p0 * 3 + 2], sp[p1 * 3 + 2]);
        dist[2 * j] = 1e10f; dist[2 * j + 1] = 1e10f;
    }

    float cx = sp[0], cy = sp[1], cz = sp[2];
    if (tid == 0) {
        float* o = out_xyz + (size_t)g * MANCH * 3;
        o[0] = cx; o[1] = cy; o[2] = cz;
    }

    for (int s = 1; s < MANCH; ++s) {
        const ull ncx2 = packf(-cx, -cx);
        const ull ncy2 = packf(-cy, -cy);
        const ull ncz2 = packf(-cz, -cz);
        float bv = -1.0f;
#pragma unroll
        for (int j = 0; j < 8; ++j) {
            // exact per-lane rn: sub == fma(p,1,-c); mul == fma(a,a,0);
            // order matches (dx*dx + dy*dy) + dz*dz with separate roundings
            ull ax = fma2(px2[j], ONE2, ncx2);
            ull ay = fma2(py2[j], ONE2, ncy2);
            ull az = fma2(pz2[j], ONE2, ncz2);
            ull mx = fma2(ax, ax, 0ull);
            ull my = fma2(ay, ay, 0ull);
            ull s1 = fma2(mx, ONE2, my);
            ull mz = fma2(az, az, 0ull);
            ull d2 = fma2(s1, ONE2, mz);
            float dlo, dhi;
            unpackf(d2, dlo, dhi);
            float n0 = fminf(dist[2 * j], dlo);
            float n1 = fminf(dist[2 * j + 1], dhi);
            dist[2 * j] = n0; dist[2 * j + 1] = n1;
            bv = fmaxf(bv, n0); bv = fmaxf(bv, n1);
        }
        unsigned wmax = __reduce_max_sync(0xffffffffu, __float_as_uint(bv));
        float wvf = __uint_as_float(wmax);
        unsigned cand = 0xffffffffu;
#pragma unroll
        for (int sl = 0; sl < 16; ++sl) {
            unsigned gi = (sl >> 1) * 512 + (sl & 1) * 256 + tid;
            if (dist[sl] == wvf) cand = min(cand, gi);
        }
        cand = __reduce_min_sync(0xffffffffu, cand);
        if (lane == 0)
            wkey[s & 1][wid] = ((ull)wmax << 32) | (unsigned)(~cand);
        __syncthreads();
        ull best = wkey[s & 1][0];
#pragma unroll
        for (int i = 1; i < 8; ++i) best = max(best, wkey[s & 1][i]);
        int wi = (int)(~(unsigned)best);
        cx = sp[wi * 3 + 0]; cy = sp[wi * 3 + 1]; cz = sp[wi * 3 + 2];
        if (tid == 0) {
            float* o = out_xyz + ((size_t)g * MANCH + s) * 3;
            o[0] = cx; o[1] = cy; o[2] = cz;
        }
    }
}

// ---------------------------------------------------------------------------
// Kernel 2: ball query -> displacement float4 (unchanged; proven)
// ---------------------------------------------------------------------------
__global__ __launch_bounds__(256) void ball_kernel(const float* __restrict__ xyzs,
                                                   const float* __restrict__ anchors) {
    const int bid = blockIdx.x;
    const int g = bid / 3, dti = bid % 3;
    const int dt = dti - 1;
    const int b = g >> 4, f = g & 15;
    int t = 2 * f + dt;
    t = min(max(t, 0), TFRAMES - 1);
    const float* fr = xyzs + (size_t)(b * TFRAMES + t) * NPTS * 3;

    __shared__ float sp[NPTS * 3];
    for (int i = threadIdx.x; i < NPTS * 3; i += 256) sp[i] = fr[i];
    __syncthreads();

    const int w = threadIdx.x >> 5;
    const int lane = threadIdx.x & 31;
    const float r2 = (float)(0.15 * 0.15);
    const float tch = (float)dt;

    for (int m = w; m < MANCH; m += 8) {
        const float* a = anchors + ((size_t)g * MANCH + m) * 3;
        const float ax = a[0], ay = a[1], az = a[2];
        float4* od = g_disp + ((size_t)(dti * GROUPS + g) * MANCH + m) * KNBR;

        int filled = 0;
        float fx = 0.f, fy = 0.f, fz = 0.f;
        bool havefirst = false;

        for (int base = 0; base < NPTS; base += 32) {
            const int j = base + lane;
            float dx = sp[j * 3 + 0] - ax;
            float dy = sp[j * 3 + 1] - ay;
            float dz = sp[j * 3 + 2] - az;
            float d2 = __fadd_rn(__fadd_rn(__fmul_rn(dx, dx), __fmul_rn(dy, dy)),
                                 __fmul_rn(dz, dz));
            bool pred = d2 < r2;
            unsigned mask = __ballot_sync(0xffffffffu, pred);
            if (mask) {
                int pos = filled + __popc(mask & ((1u << lane) - 1u));
                if (pred && pos < KNBR) od[pos] = make_float4(dx, dy, dz, tch);
                if (!havefirst) {
                    int src = __ffs(mask) - 1;
                    fx = __shfl_sync(0xffffffffu, dx, src);
                    fy = __shfl_sync(0xffffffffu, dy, src);
                    fz = __shfl_sync(0xffffffffu, dz, src);
                    havefirst = true;
                }
                filled += __popc(mask);
                if (filled >= KNBR) break;
            }
        }
        if (filled < KNBR) {
            if (!havefirst) {
                fx = sp[0] - ax; fy = sp[1] - ay; fz = sp[2] - az;
            }
            int s = filled + lane;
            if (s < KNBR) od[s] = make_float4(fx, fy, fz, tch);
        }
    }
}

// ---------------------------------------------------------------------------
// Kernel 3: MLP via mma.sync m16n8k16 bf16 (3-pass split), ldmatrix B-frags,
// double-buffered h (ONE barrier per iter).
// ---------------------------------------------------------------------------
#define HBW 36    // words per h-row (144 B) -> ldmatrix conflict-free

__device__ __forceinline__ void split2(float v0, float v1, uint32_t& hi, uint32_t& lo) {
    __nv_bfloat162 h2 = __floats2bfloat162_rn(v0, v1);   // .x = v0 (low half)
    hi = *(uint32_t*)&h2;
    float h0f = __uint_as_float(hi << 16);
    float h1f = __uint_as_float(hi & 0xffff0000u);
    __nv_bfloat162 l2 = __floats2bfloat162_rn(v0 - h0f, v1 - h1f);
    lo = *(uint32_t*)&l2;
}

#define MMA_BF16(d, a, b0, b1)                                                  \
    asm("mma.sync.aligned.m16n8k16.row.col.f32.bf16.bf16.f32 "                  \
        "{%0,%1,%2,%3}, {%4,%5,%6,%7}, {%8,%9}, {%0,%1,%2,%3};"                 \
        : "+f"((d)[0]), "+f"((d)[1]), "+f"((d)[2]), "+f"((d)[3])                \
        : "r"((a)[0]), "r"((a)[1]), "r"((a)[2]), "r"((a)[3]), "r"(b0), "r"(b1))

#define LDM_X4(r0, r1, r2, r3, addr)                                            \
    asm volatile("ldmatrix.sync.aligned.m8n8.x4.shared.b16 {%0,%1,%2,%3}, [%4];" \
        : "=r"(r0), "=r"(r1), "=r"(r2), "=r"(r3) : "r"(addr))

__global__ __launch_bounds__(128, 1) void mlp_kernel(const float* __restrict__ Wd,
                                                     const float* __restrict__ Wm,
                                                     float* __restrict__ out) {
    __shared__ float4   s_wd[C0];                         // 1 KB
    __shared__ __align__(16) uint32_t s_hb[2][2][64 * HBW]; // [hi/lo][buf] 36 KB
    __shared__ float    s_obuf[C1 * 16];                  // 8 KB

    const int tid = threadIdx.x;
    const int w = tid >> 5, lane = tid & 31;
    const int q = lane & 3, nl = lane >> 2;
    const int g = blockIdx.x >> 3;
    const int m_base = (blockIdx.x & 7) * 16;

    if (tid < C0) s_wd[tid] = ((const float4*)Wd)[tid];

    // Wm split fragments in registers
    uint32_t Ahi[2][4][4], Alo[2][4][4];
#pragma unroll
    for (int rr = 0; rr < 4; ++rr) {
        const int r = 32 * w + 16 * (rr >> 1) + 8 * (rr & 1) + nl;
        const float* wr = Wm + (size_t)r * C0;
#pragma unroll
        for (int kt = 0; kt < 4; ++kt)
#pragma unroll
            for (int hf = 0; hf < 2; ++hf) {
                float2 v = *(const float2*)(wr + kt * 16 + 8 * hf + 2 * q);
                split2(v.x, v.y, Ahi[rr >> 1][kt][(rr & 1) + 2 * hf],
                                 Alo[rr >> 1][kt][(rr & 1) + 2 * hf]);
            }
    }
    __syncthreads();

    // producer mapping
    const int l1_a  = tid >> 6;
    const int l1_k  = (tid >> 1) & 31;
    const int l1_ch = tid & 1;
    const int prow  = l1_a * 32 + l1_k;
    const float4* wd_half = s_wd + l1_ch * 32;

    // ldmatrix lane base: row (lane&7), tile (lane>>3)*16B
    const uint32_t hb0 = (uint32_t)__cvta_generic_to_shared(&s_hb[0][0][0]);
    const uint32_t laneoff = (uint32_t)((lane & 7) * (HBW * 4) + (lane >> 3) * 16);
    const uint32_t BUFB = 64 * HBW * 4;   // 9216 bytes per [hi/lo][buf]

    float fsum[2][2][2];
#pragma unroll
    for (int i = 0; i < 8; ++i) (&fsum[0][0][0])[i] = 0.f;

    for (int pair = 0; pair < 8; ++pair) {
        for (int dti = 0; dti < 3; ++dti) {
            const int t = pair * 3 + dti;
            const int buf = t & 1;
            // ---- produce layer-1 h into s_hb[.][buf] ----
            {
                const int m = m_base + pair * 2 + l1_a;
                float4 dv = g_disp[((size_t)(dti * GROUPS + g) * MANCH + m) * KNBR + l1_k];
                uint32_t* hh = &s_hb[0][buf][prow * HBW + l1_ch * 16];
                uint32_t* hl = &s_hb[1][buf][prow * HBW + l1_ch * 16];
#pragma unroll
                for (int j = 0; j < 16; ++j) {
                    float4 w0 = wd_half[2 * j], w1 = wd_half[2 * j + 1];
                    float h0 = fmaxf(fmaf(w0.w, dv.w, fmaf(w0.z, dv.z,
                                     fmaf(w0.y, dv.y, w0.x * dv.x))), 0.f);
                    float h1 = fmaxf(fmaf(w1.w, dv.w, fmaf(w1.z, dv.z,
                                     fmaf(w1.y, dv.y, w1.x * dv.x))), 0.f);
                    split2(h0, h1, hh[j], hl[j]);
                }
            }
            __syncthreads();   // single barrier per iter (double-buffered h)

            // ---- consume: MMAs with ldmatrix B fragments ----
            float acc[2][8][4];
#pragma unroll
            for (int i = 0; i < 64; ++i) (&acc[0][0][0])[i] = 0.f;
            const uint32_t ahi = hb0 + (uint32_t)buf * BUFB + laneoff;
            const uint32_t alo = hb0 + (2u + buf) * BUFB + laneoff;
#pragma unroll
            for (int nt = 0; nt < 8; ++nt) {
                uint32_t bh[8], bl[8];
                const uint32_t ro = (uint32_t)(nt * 8 * HBW * 4);
                LDM_X4(bh[0], bh[1], bh[2], bh[3], ahi + ro);
                LDM_X4(bh[4], bh[5], bh[6], bh[7], ahi + ro + 64);
                LDM_X4(bl[0], bl[1], bl[2], bl[3], alo + ro);
                LDM_X4(bl[4], bl[5], bl[6], bl[7], alo + ro + 64);
#pragma unroll
                for (int kt = 0; kt < 4; ++kt) {
#pragma unroll
                    for (int mt = 0; mt < 2; ++mt) {
                        MMA_BF16(acc[mt][nt], Ahi[mt][kt], bh[2 * kt], bh[2 * kt + 1]);
                        MMA_BF16(acc[mt][nt], Ahi[mt][kt], bl[2 * kt], bl[2 * kt + 1]);
                        MMA_BF16(acc[mt][nt], Alo[mt][kt], bh[2 * kt], bh[2 * kt + 1]);
                    }
                }
            }

            // ---- epilogue: max over k, relu, accumulate over dt ----
#pragma unroll
            for (int mt = 0; mt < 2; ++mt)
#pragma unroll
                for (int a = 0; a < 2; ++a) {
                    float m0 = -1e30f, m1 = -1e30f;
#pragma unroll
                    for (int nt = a * 4; nt < a * 4 + 4; ++nt) {
                        m0 = fmaxf(m0, fmaxf(acc[mt][nt][0], acc[mt][nt][1]));
                        m1 = fmaxf(m1, fmaxf(acc[mt][nt][2], acc[mt][nt][3]));
                    }
                    m0 = fmaxf(m0, __shfl_xor_sync(0xffffffffu, m0, 1));
                    m0 = fmaxf(m0, __shfl_xor_sync(0xffffffffu, m0, 2));
                    m1 = fmaxf(m1, __shfl_xor_sync(0xffffffffu, m1, 1));
                    m1 = fmaxf(m1, __shfl_xor_sync(0xffffffffu, m1, 2));
                    fsum[mt][0][a] += fmaxf(m0, 0.f);
                    fsum[mt][1][a] += fmaxf(m1, 0.f);
                }
        }
        if (q == 0) {
#pragma unroll
            for (int mt = 0; mt < 2; ++mt)
#pragma unroll
                for (int rh = 0; rh < 2; ++rh)
#pragma unroll
                    for (int a = 0; a < 2; ++a) {
                        int o = 32 * w + 16 * mt + 8 * rh + nl;
                        s_obuf[o * 16 + pair * 2 + a] = fsum[mt][rh][a];
                    }
        }
#pragma unroll
        for (int i = 0; i < 8; ++i) (&fsum[0][0][0])[i] = 0.f;
    }
    __syncthreads();

    float4* dst = (float4*)(out + 24576 + ((size_t)g * C1 + tid) * MANCH + m_base);
    const float4* src = (const float4*)(s_obuf + tid * 16);
#pragma unroll
    for (int i = 0; i < 4; ++i) dst[i] = src[i];
}

// ---------------------------------------------------------------------------
extern "C" void kernel_launch(void* const* d_in, const int* in_sizes, int n_in,
                              void* d_out, int out_size) {
    const float* xyzs = (const float*)d_in[0];
    const float* Wd   = (const float*)d_in[1];
    const float* Wm   = (const float*)d_in[2];
    float* out = (float*)d_out;

    fps_kernel<<<GROUPS, 256>>>(xyzs, out);
    ball_kernel<<<GROUPS * 3, 256>>>(xyzs, out);
    mlp_kernel<<<GROUPS * 8, 128>>>(Wd, Wm, out);
}

// round 6
// speedup vs baseline: 2.0500x; 1.1202x over previous
#include <cuda_runtime.h>
#include <cuda_bf16.h>
#include <cuda_fp16.h>
#include <cstdint>

#define BATCH   4
#define TFRAMES 32
#define NPTS    4096
#define FOUT    16
#define GROUPS  64
#define MANCH   128
#define KNBR    32
#define C0      64
#define C1      128

__device__ float4 g_disp[3 * GROUPS * MANCH * KNBR];   // 12.58 MB scratch

typedef unsigned long long ull;

__device__ __forceinline__ ull fma2(ull a, ull b, ull c) {
    ull d;
    asm("fma.rn.f32x2 %0, %1, %2, %3;" : "=l"(d) : "l"(a), "l"(b), "l"(c));
    return d;
}
__device__ __forceinline__ ull packf(float lo, float hi) {
    ull r;
    asm("mov.b64 %0, {%1, %2};" : "=l"(r) : "f"(lo), "f"(hi));
    return r;
}
__device__ __forceinline__ void unpackf(ull v, float& lo, float& hi) {
    asm("mov.b64 {%0, %1}, %2;" : "=f"(lo), "=f"(hi) : "l"(v));
}

// ---------------------------------------------------------------------------
// Kernel 1: FPS. 512 threads, 8 pts/thread (4 f32x2 pairs), one barrier/iter.
// ---------------------------------------------------------------------------
__global__ __launch_bounds__(512) void fps_kernel(const float* __restrict__ xyzs,
                                                  float* __restrict__ out_xyz) {
    const int g = blockIdx.x;
    const int b = g >> 4, f = g & 15;
    const float* fr = xyzs + ((size_t)(b * TFRAMES + 2 * f) * NPTS) * 3;
    const int tid = threadIdx.x;
    const int wid = tid >> 5, lane = tid & 31;

    __shared__ float sp[NPTS * 3];                 // 48 KB
    __shared__ ull wkey[2][16];
    for (int i = tid; i < NPTS * 3; i += 512) sp[i] = fr[i];
    __syncthreads();

    const ull ONE2 = packf(1.0f, 1.0f);
    ull px2[4], py2[4], pz2[4];
    float dist[8];
#pragma unroll
    for (int j = 0; j < 4; ++j) {
        int p0 = j * 1024 + tid, p1 = p0 + 512;
        px2[j] = packf(sp[p0 * 3 + 0], sp[p1 * 3 + 0]);
        py2[j] = packf(sp[p0 * 3 + 1], sp[p1 * 3 + 1]);
        pz2[j] = packf(sp[p0 * 3 + 2], sp[p1 * 3 + 2]);
        dist[2 * j] = 1e10f; dist[2 * j + 1] = 1e10f;
    }

    float cx = sp[0], cy = sp[1], cz = sp[2];
    if (tid == 0) {
        float* o = out_xyz + (size_t)g * MANCH * 3;
        o[0] = cx; o[1] = cy; o[2] = cz;
    }

    for (int s = 1; s < MANCH; ++s) {
        const ull ncx2 = packf(-cx, -cx);
        const ull ncy2 = packf(-cy, -cy);
        const ull ncz2 = packf(-cz, -cz);
#pragma unroll
        for (int j = 0; j < 4; ++j) {
            // exact rn per lane; order = (dx*dx + dy*dy) + dz*dz
            ull ax = fma2(px2[j], ONE2, ncx2);
            ull ay = fma2(py2[j], ONE2, ncy2);
            ull az = fma2(pz2[j], ONE2, ncz2);
            ull mx = fma2(ax, ax, 0ull);
            ull my = fma2(ay, ay, 0ull);
            ull s1 = fma2(mx, ONE2, my);
            ull mz = fma2(az, az, 0ull);
            ull d2 = fma2(s1, ONE2, mz);
            float dlo, dhi;
            unpackf(d2, dlo, dhi);
            dist[2 * j]     = fminf(dist[2 * j], dlo);
            dist[2 * j + 1] = fminf(dist[2 * j + 1], dhi);
        }
        // tree max over 8 slots
        float m0 = fmaxf(dist[0], dist[1]);
        float m1 = fmaxf(dist[2], dist[3]);
        float m2 = fmaxf(dist[4], dist[5]);
        float m3 = fmaxf(dist[6], dist[7]);
        float bv = fmaxf(fmaxf(m0, m1), fmaxf(m2, m3));
        unsigned wmax = __reduce_max_sync(0xffffffffu, __float_as_uint(bv));
        float wvf = __uint_as_float(wmax);
        unsigned cand = 0xffffffffu;
#pragma unroll
        for (int sl = 0; sl < 8; ++sl) {
            unsigned gi = (sl >> 1) * 1024 + (sl & 1) * 512 + tid;
            if (dist[sl] == wvf) cand = min(cand, gi);
        }
        cand = __reduce_min_sync(0xffffffffu, cand);
        if (lane == 0)
            wkey[s & 1][wid] = ((ull)wmax << 32) | (unsigned)(~cand);
        __syncthreads();
        const ull* kk = wkey[s & 1];
        ull b0 = max(kk[0], kk[1]),  b1 = max(kk[2], kk[3]);
        ull b2 = max(kk[4], kk[5]),  b3 = max(kk[6], kk[7]);
        ull b4 = max(kk[8], kk[9]),  b5 = max(kk[10], kk[11]);
        ull b6 = max(kk[12], kk[13]), b7 = max(kk[14], kk[15]);
        ull best = max(max(max(b0, b1), max(b2, b3)),
                       max(max(b4, b5), max(b6, b7)));
        int wi = (int)(~(unsigned)best);
        cx = sp[wi * 3 + 0]; cy = sp[wi * 3 + 1]; cz = sp[wi * 3 + 2];
        if (tid == 0) {
            float* o = out_xyz + ((size_t)g * MANCH + s) * 3;
            o[0] = cx; o[1] = cy; o[2] = cz;
        }
    }
}

// ---------------------------------------------------------------------------
// Kernel 2: ball query -> displacement float4 (unchanged; proven)
// ---------------------------------------------------------------------------
__global__ __launch_bounds__(256) void ball_kernel(const float* __restrict__ xyzs,
                                                   const float* __restrict__ anchors) {
    const int bid = blockIdx.x;
    const int g = bid / 3, dti = bid % 3;
    const int dt = dti - 1;
    const int b = g >> 4, f = g & 15;
    int t = 2 * f + dt;
    t = min(max(t, 0), TFRAMES - 1);
    const float* fr = xyzs + (size_t)(b * TFRAMES + t) * NPTS * 3;

    __shared__ float sp[NPTS * 3];
    for (int i = threadIdx.x; i < NPTS * 3; i += 256) sp[i] = fr[i];
    __syncthreads();

    const int w = threadIdx.x >> 5;
    const int lane = threadIdx.x & 31;
    const float r2 = (float)(0.15 * 0.15);
    const float tch = (float)dt;

    for (int m = w; m < MANCH; m += 8) {
        const float* a = anchors + ((size_t)g * MANCH + m) * 3;
        const float ax = a[0], ay = a[1], az = a[2];
        float4* od = g_disp + ((size_t)(dti * GROUPS + g) * MANCH + m) * KNBR;

        int filled = 0;
        float fx = 0.f, fy = 0.f, fz = 0.f;
        bool havefirst = false;

        for (int base = 0; base < NPTS; base += 32) {
            const int j = base + lane;
            float dx = sp[j * 3 + 0] - ax;
            float dy = sp[j * 3 + 1] - ay;
            float dz = sp[j * 3 + 2] - az;
            float d2 = __fadd_rn(__fadd_rn(__fmul_rn(dx, dx), __fmul_rn(dy, dy)),
                                 __fmul_rn(dz, dz));
            bool pred = d2 < r2;
            unsigned mask = __ballot_sync(0xffffffffu, pred);
            if (mask) {
                int pos = filled + __popc(mask & ((1u << lane) - 1u));
                if (pred && pos < KNBR) od[pos] = make_float4(dx, dy, dz, tch);
                if (!havefirst) {
                    int src = __ffs(mask) - 1;
                    fx = __shfl_sync(0xffffffffu, dx, src);
                    fy = __shfl_sync(0xffffffffu, dy, src);
                    fz = __shfl_sync(0xffffffffu, dz, src);
                    havefirst = true;
                }
                filled += __popc(mask);
                if (filled >= KNBR) break;
            }
        }
        if (filled < KNBR) {
            if (!havefirst) {
                fx = sp[0] - ax; fy = sp[1] - ay; fz = sp[2] - az;
            }
            int s = filled + lane;
            if (s < KNBR) od[s] = make_float4(fx, fy, fz, tch);
        }
    }
}

// ---------------------------------------------------------------------------
// Kernel 3: MLP via mma.sync m16n8k16 fp16, A (Wm) split hi+lo (2 passes),
// B (h) single fp16. Double-buffered h, ldmatrix B-frags.
// ---------------------------------------------------------------------------
#define HBW 36    // words per h-row (144 B; 64 halves data + pad)

#define MMA_F16(d, a, b0, b1)                                                   \
    asm("mma.sync.aligned.m16n8k16.row.col.f32.f16.f16.f32 "                    \
        "{%0,%1,%2,%3}, {%4,%5,%6,%7}, {%8,%9}, {%0,%1,%2,%3};"                 \
        : "+f"((d)[0]), "+f"((d)[1]), "+f"((d)[2]), "+f"((d)[3])                \
        : "r"((a)[0]), "r"((a)[1]), "r"((a)[2]), "r"((a)[3]), "r"(b0), "r"(b1))

#define LDM_X4(r0, r1, r2, r3, addr)                                            \
    asm volatile("ldmatrix.sync.aligned.m8n8.x4.shared.b16 {%0,%1,%2,%3}, [%4];" \
        : "=r"(r0), "=r"(r1), "=r"(r2), "=r"(r3) : "r"(addr))

__global__ __launch_bounds__(128, 2) void mlp_kernel(const float* __restrict__ Wd,
                                                     const float* __restrict__ Wm,
                                                     float* __restrict__ out) {
    __shared__ float4   s_wd[C0];                           // 1 KB
    __shared__ __align__(16) uint32_t s_hb[2][64 * HBW];    // [buf] 18 KB, fp16 h
    __shared__ float    s_obuf[C1 * 16];                    // 8 KB

    const int tid = threadIdx.x;
    const int w = tid >> 5, lane = tid & 31;
    const int q = lane & 3, nl = lane >> 2;
    const int g = blockIdx.x >> 3;
    const int m_base = (blockIdx.x & 7) * 16;

    if (tid < C0) s_wd[tid] = ((const float4*)Wd)[tid];

    // Wm -> exact fp16 hi/lo fragments in registers
    uint32_t Ah[2][4][4], Al[2][4][4];
#pragma unroll
    for (int rr = 0; rr < 4; ++rr) {
        const int r = 32 * w + 16 * (rr >> 1) + 8 * (rr & 1) + nl;
        const float* wr = Wm + (size_t)r * C0;
#pragma unroll
        for (int kt = 0; kt < 4; ++kt)
#pragma unroll
            for (int hf = 0; hf < 2; ++hf) {
                float2 v = *(const float2*)(wr + kt * 16 + 8 * hf + 2 * q);
                __half2 h2 = __floats2half2_rn(v.x, v.y);
                __half2 l2 = __floats2half2_rn(v.x - __low2float(h2),
                                               v.y - __high2float(h2));
                Ah[rr >> 1][kt][(rr & 1) + 2 * hf] = *(uint32_t*)&h2;
                Al[rr >> 1][kt][(rr & 1) + 2 * hf] = *(uint32_t*)&l2;
            }
    }
    __syncthreads();

    // producer mapping: thread -> (anchor-in-pair, k, channel-half)
    const int l1_a  = tid >> 6;
    const int l1_k  = (tid >> 1) & 31;
    const int l1_ch = tid & 1;
    const int prow  = l1_a * 32 + l1_k;
    const float4* wd_half = s_wd + l1_ch * 32;

    const uint32_t hb0 = (uint32_t)__cvta_generic_to_shared(&s_hb[0][0]);
    const uint32_t laneoff = (uint32_t)((lane & 7) * (HBW * 4) + (lane >> 3) * 16);
    const uint32_t BUFB = 64 * HBW * 4;

    float fsum[2][2][2];
#pragma unroll
    for (int i = 0; i < 8; ++i) (&fsum[0][0][0])[i] = 0.f;

    for (int pair = 0; pair < 8; ++pair) {
        for (int dti = 0; dti < 3; ++dti) {
            const int t = pair * 3 + dti;
            const int buf = t & 1;
            // ---- produce layer-1 h (fp16) into s_hb[buf] ----
            {
                const int m = m_base + pair * 2 + l1_a;
                float4 dv = g_disp[((size_t)(dti * GROUPS + g) * MANCH + m) * KNBR + l1_k];
                uint32_t* hrow = &s_hb[buf][prow * HBW + l1_ch * 16];
#pragma unroll
                for (int j = 0; j < 16; ++j) {
                    float4 w0 = wd_half[2 * j], w1 = wd_half[2 * j + 1];
                    float h0 = fmaxf(fmaf(w0.w, dv.w, fmaf(w0.z, dv.z,
                                     fmaf(w0.y, dv.y, w0.x * dv.x))), 0.f);
                    float h1 = fmaxf(fmaf(w1.w, dv.w, fmaf(w1.z, dv.z,
                                     fmaf(w1.y, dv.y, w1.x * dv.x))), 0.f);
                    __half2 p = __floats2half2_rn(h0, h1);
                    hrow[j] = *(uint32_t*)&p;
                }
            }
            __syncthreads();

            // ---- consume: 2-pass MMA with ldmatrix B fragments ----
            float acc[2][8][4];
#pragma unroll
            for (int i = 0; i < 64; ++i) (&acc[0][0][0])[i] = 0.f;
            const uint32_t ab = hb0 + (uint32_t)buf * BUFB + laneoff;
#pragma unroll
            for (int nt = 0; nt < 8; ++nt) {
                uint32_t bf[8];
                const uint32_t ro = (uint32_t)(nt * 8 * HBW * 4);
                LDM_X4(bf[0], bf[1], bf[2], bf[3], ab + ro);
                LDM_X4(bf[4], bf[5], bf[6], bf[7], ab + ro + 64);
#pragma unroll
                for (int kt = 0; kt < 4; ++kt) {
#pragma unroll
                    for (int mt = 0; mt < 2; ++mt) {
                        MMA_F16(acc[mt][nt], Ah[mt][kt], bf[2 * kt], bf[2 * kt + 1]);
                        MMA_F16(acc[mt][nt], Al[mt][kt], bf[2 * kt], bf[2 * kt + 1]);
                    }
                }
            }

            // ---- epilogue: max over k, relu, accumulate over dt ----
#pragma unroll
            for (int mt = 0; mt < 2; ++mt)
#pragma unroll
                for (int a = 0; a < 2; ++a) {
                    float m0 = -1e30f, m1 = -1e30f;
#pragma unroll
                    for (int nt = a * 4; nt < a * 4 + 4; ++nt) {
                        m0 = fmaxf(m0, fmaxf(acc[mt][nt][0], acc[mt][nt][1]));
                        m1 = fmaxf(m1, fmaxf(acc[mt][nt][2], acc[mt][nt][3]));
                    }
                    m0 = fmaxf(m0, __shfl_xor_sync(0xffffffffu, m0, 1));
                    m0 = fmaxf(m0, __shfl_xor_sync(0xffffffffu, m0, 2));
                    m1 = fmaxf(m1, __shfl_xor_sync(0xffffffffu, m1, 1));
                    m1 = fmaxf(m1, __shfl_xor_sync(0xffffffffu, m1, 2));
                    fsum[mt][0][a] += fmaxf(m0, 0.f);
                    fsum[mt][1][a] += fmaxf(m1, 0.f);
                }
        }
        if (q == 0) {
#pragma unroll
            for (int mt = 0; mt < 2; ++mt)
#pragma unroll
                for (int rh = 0; rh < 2; ++rh)
#pragma unroll
                    for (int a = 0; a < 2; ++a) {
                        int o = 32 * w + 16 * mt + 8 * rh + nl;
                        s_obuf[o * 16 + pair * 2 + a] = fsum[mt][rh][a];
                    }
        }
#pragma unroll
        for (int i = 0; i < 8; ++i) (&fsum[0][0][0])[i] = 0.f;
    }
    __syncthreads();

    float4* dst = (float4*)(out + 24576 + ((size_t)g * C1 + tid) * MANCH + m_base);
    const float4* src = (const float4*)(s_obuf + tid * 16);
#pragma unroll
    for (int i = 0; i < 4; ++i) dst[i] = src[i];
}

// ---------------------------------------------------------------------------
extern "C" void kernel_launch(void* const* d_in, const int* in_sizes, int n_in,
                              void* d_out, int out_size) {
    const float* xyzs = (const float*)d_in[0];
    const float* Wd   = (const float*)d_in[1];
    const float* Wm   = (const float*)d_in[2];
    float* out = (float*)d_out;

    fps_kernel<<<GROUPS, 512>>>(xyzs, out);
    ball_kernel<<<GROUPS * 3, 256>>>(xyzs, out);
    mlp_kernel<<<GROUPS * 8, 128>>>(Wd, Wm, out);
}

// round 8
// speedup vs baseline: 2.3645x; 1.1534x over previous
#include <cuda_runtime.h>
#include <cuda_bf16.h>
#include <cuda_fp16.h>
#include <cstdint>

#define BATCH   4
#define TFRAMES 32
#define NPTS    4096
#define FOUT    16
#define GROUPS  64
#define MANCH   128
#define KNBR    32
#define C0      64
#define C1      128

__device__ float4 g_disp[3 * GROUPS * MANCH * KNBR];   // 12.58 MB scratch

typedef unsigned long long ull;

__device__ __forceinline__ ull fma2(ull a, ull b, ull c) {
    ull d;
    asm("fma.rn.f32x2 %0, %1, %2, %3;" : "=l"(d) : "l"(a), "l"(b), "l"(c));
    return d;
}
__device__ __forceinline__ ull packf(float lo, float hi) {
    ull r;
    asm("mov.b64 %0, {%1, %2};" : "=l"(r) : "f"(lo), "f"(hi));
    return r;
}
__device__ __forceinline__ void unpackf(ull v, float& lo, float& hi) {
    asm("mov.b64 {%0, %1}, %2;" : "=f"(lo), "=f"(hi) : "l"(v));
}

// ---------------------------------------------------------------------------
// Kernel 1: FPS. 256 threads, 16 pts/thread (8 f32x2 pairs), one barrier/iter,
// cross-warp combine via single smem atomicMax (3-slot rotation).
// ---------------------------------------------------------------------------
__global__ __launch_bounds__(256) void fps_kernel(const float* __restrict__ xyzs,
                                                  float* __restrict__ out_xyz) {
    const int g = blockIdx.x;
    const int b = g >> 4, f = g & 15;
    const float* fr = xyzs + ((size_t)(b * TFRAMES + 2 * f) * NPTS) * 3;
    const int tid = threadIdx.x;
    const int lane = tid & 31;

    __shared__ float sp[NPTS * 3];                 // 48 KB
    __shared__ ull best[3];
    for (int i = tid; i < NPTS * 3; i += 256) sp[i] = fr[i];
    if (tid < 3) best[tid] = 0ull;
    __syncthreads();

    const ull ONE2 = packf(1.0f, 1.0f);
    ull px2[8], py2[8], pz2[8];
    float dist[16];
#pragma unroll
    for (int j = 0; j < 8; ++j) {
        int p0 = j * 512 + tid, p1 = p0 + 256;
        px2[j] = packf(sp[p0 * 3 + 0], sp[p1 * 3 + 0]);
        py2[j] = packf(sp[p0 * 3 + 1], sp[p1 * 3 + 1]);
        pz2[j] = packf(sp[p0 * 3 + 2], sp[p1 * 3 + 2]);
        dist[2 * j] = 1e10f; dist[2 * j + 1] = 1e10f;
    }

    float cx = sp[0], cy = sp[1], cz = sp[2];
    if (tid == 0) {
        float* o = out_xyz + (size_t)g * MANCH * 3;
        o[0] = cx; o[1] = cy; o[2] = cz;
    }

    for (int s = 1; s < MANCH; ++s) {
        const ull ncx2 = packf(-cx, -cx);
        const ull ncy2 = packf(-cy, -cy);
        const ull ncz2 = packf(-cz, -cz);
#pragma unroll
        for (int j = 0; j < 8; ++j) {
            ull ax = fma2(px2[j], ONE2, ncx2);
            ull ay = fma2(py2[j], ONE2, ncy2);
            ull az = fma2(pz2[j], ONE2, ncz2);
            ull mx = fma2(ax, ax, 0ull);
            ull my = fma2(ay, ay, 0ull);
            ull s1 = fma2(mx, ONE2, my);
            ull mz = fma2(az, az, 0ull);
            ull d2 = fma2(s1, ONE2, mz);
            float dlo, dhi;
            unpackf(d2, dlo, dhi);
            dist[2 * j]     = fminf(dist[2 * j], dlo);
            dist[2 * j + 1] = fminf(dist[2 * j + 1], dhi);
        }
        float t0 = fmaxf(fmaxf(dist[0], dist[1]),  fmaxf(dist[2], dist[3]));
        float t1 = fmaxf(fmaxf(dist[4], dist[5]),  fmaxf(dist[6], dist[7]));
        float t2 = fmaxf(fmaxf(dist[8], dist[9]),  fmaxf(dist[10], dist[11]));
        float t3 = fmaxf(fmaxf(dist[12], dist[13]), fmaxf(dist[14], dist[15]));
        float bv = fmaxf(fmaxf(t0, t1), fmaxf(t2, t3));
        unsigned wmax = __reduce_max_sync(0xffffffffu, __float_as_uint(bv));
        float wvf = __uint_as_float(wmax);
        unsigned cand = 0xffffffffu;
#pragma unroll
        for (int sl = 0; sl < 16; ++sl) {
            unsigned gi = (sl >> 1) * 512 + (sl & 1) * 256 + tid;
            if (dist[sl] == wvf) cand = min(cand, gi);
        }
        cand = __reduce_min_sync(0xffffffffu, cand);
        const int slot = s % 3;
        if (lane == 0)
            atomicMax(&best[slot], ((ull)wmax << 32) | (unsigned)(~cand));
        __syncthreads();
        int wi = (int)(~(unsigned)best[slot]);
        cx = sp[wi * 3 + 0]; cy = sp[wi * 3 + 1]; cz = sp[wi * 3 + 2];
        if (tid == 0) {
            best[(s + 2) % 3] = 0ull;              // reset 2 iters ahead
            float* o = out_xyz + ((size_t)g * MANCH + s) * 3;
            o[0] = cx; o[1] = cy; o[2] = cz;
        }
    }
}

// ---------------------------------------------------------------------------
// Kernel 2: ball query. Transposed smem planes, 4 points/lane (LD.128),
// packed f32x2 distances (identical rn order), 4-mask ordered slots.
// ---------------------------------------------------------------------------
__global__ __launch_bounds__(256) void ball_kernel(const float* __restrict__ xyzs,
                                                   const float* __restrict__ anchors) {
    const int bid = blockIdx.x;
    const int g = bid / 3, dti = bid % 3;
    const int dt = dti - 1;
    const int b = g >> 4, f = g & 15;
    int t = 2 * f + dt;
    t = min(max(t, 0), TFRAMES - 1);
    const float* fr = xyzs + (size_t)(b * TFRAMES + t) * NPTS * 3;

    __shared__ float sx[NPTS], sy[NPTS], sz[NPTS];   // 48 KB transposed
    for (int p = threadIdx.x; p < NPTS; p += 256) {
        const float* pp = fr + p * 3;
        sx[p] = pp[0]; sy[p] = pp[1]; sz[p] = pp[2];
    }
    __syncthreads();

    const int w = threadIdx.x >> 5;
    const int lane = threadIdx.x & 31;
    const float r2 = (float)(0.15 * 0.15);
    const float tch = (float)dt;
    const ull ONE2 = packf(1.0f, 1.0f);
    const unsigned below = (1u << lane) - 1u;

    for (int m = w; m < MANCH; m += 8) {
        const float* a = anchors + ((size_t)g * MANCH + m) * 3;
        const float ax = a[0], ay = a[1], az = a[2];
        const ull nax2 = packf(-ax, -ax);
        const ull nay2 = packf(-ay, -ay);
        const ull naz2 = packf(-az, -az);
        float4* od = g_disp + ((size_t)(dti * GROUPS + g) * MANCH + m) * KNBR;

        int filled = 0;
        int firstidx = -1;

        for (int base = 0; base < NPTS; base += 128) {
            const int j0 = base + 4 * lane;
            float4 X = *(const float4*)(sx + j0);
            float4 Y = *(const float4*)(sy + j0);
            float4 Z = *(const float4*)(sz + j0);
            ull dxa = fma2(packf(X.x, X.y), ONE2, nax2);
            ull dxb = fma2(packf(X.z, X.w), ONE2, nax2);
            ull dya = fma2(packf(Y.x, Y.y), ONE2, nay2);
            ull dyb = fma2(packf(Y.z, Y.w), ONE2, nay2);
            ull dza = fma2(packf(Z.x, Z.y), ONE2, naz2);
            ull dzb = fma2(packf(Z.z, Z.w), ONE2, naz2);
            ull s1a = fma2(fma2(dxa, dxa, 0ull), ONE2, fma2(dya, dya, 0ull));
            ull s1b = fma2(fma2(dxb, dxb, 0ull), ONE2, fma2(dyb, dyb, 0ull));
            ull d2a = fma2(s1a, ONE2, fma2(dza, dza, 0ull));
            ull d2b = fma2(s1b, ONE2, fma2(dzb, dzb, 0ull));
            float d0, d1, d2, d3;
            unpackf(d2a, d0, d1);
            unpackf(d2b, d2, d3);
            bool p0 = d0 < r2, p1 = d1 < r2, p2 = d2 < r2, p3 = d3 < r2;
            unsigned m0 = __ballot_sync(0xffffffffu, p0);
            unsigned m1 = __ballot_sync(0xffffffffu, p1);
            unsigned m2 = __ballot_sync(0xffffffffu, p2);
            unsigned m3 = __ballot_sync(0xffffffffu, p3);
            unsigned anyh = m0 | m1 | m2 | m3;
            if (anyh) {
                int pos = filled + __popc(m0 & below) + __popc(m1 & below)
                                 + __popc(m2 & below) + __popc(m3 & below);
                float x0, x1, y0, y1, z0, z1, x2, x3, y2, y3, z2, z3;
                unpackf(dxa, x0, x1); unpackf(dya, y0, y1); unpackf(dza, z0, z1);
                unpackf(dxb, x2, x3); unpackf(dyb, y2, y3); unpackf(dzb, z2, z3);
                if (p0) { if (pos < KNBR) od[pos] = make_float4(x0, y0, z0, tch); pos++; }
                if (p1) { if (pos < KNBR) od[pos] = make_float4(x1, y1, z1, tch); pos++; }
                if (p2) { if (pos < KNBR) od[pos] = make_float4(x2, y2, z2, tch); pos++; }
                if (p3) { if (pos < KNBR) od[pos] = make_float4(x3, y3, z3, tch); pos++; }
                if (firstidx < 0) {
                    unsigned i0 = m0 ? 4u * (__ffs(m0) - 1)     : 0xffffu;
                    unsigned i1 = m1 ? 4u * (__ffs(m1) - 1) + 1 : 0xffffu;
                    unsigned i2 = m2 ? 4u * (__ffs(m2) - 1) + 2 : 0xffffu;
                    unsigned i3 = m3 ? 4u * (__ffs(m3) - 1) + 3 : 0xffffu;
                    firstidx = base + (int)min(min(i0, i1), min(i2, i3));
                }
                filled += __popc(m0) + __popc(m1) + __popc(m2) + __popc(m3);
                if (filled >= KNBR) break;
            }
        }
        if (filled < KNBR) {
            int fi = (firstidx < 0) ? 0 : firstidx;
            float fx = sx[fi] - ax, fy = sy[fi] - ay, fz = sz[fi] - az;
            int s = filled + lane;
            if (s < KNBR) od[s] = make_float4(fx, fy, fz, tch);
        }
    }
}

// ---------------------------------------------------------------------------
// Kernel 3: MLP via mma.sync m16n8k16 fp16, A split hi+lo (2 passes),
// packed-f32x2 producer, nt-paired MMA interleave, double-buffered h.
// ---------------------------------------------------------------------------
#define HBW 36

#define MMA_F16(d, a, b0, b1)                                                   \
    asm("mma.sync.aligned.m16n8k16.row.col.f32.f16.f16.f32 "                    \
        "{%0,%1,%2,%3}, {%4,%5,%6,%7}, {%8,%9}, {%0,%1,%2,%3};"                 \
        : "+f"((d)[0]), "+f"((d)[1]), "+f"((d)[2]), "+f"((d)[3])                \
        : "r"((a)[0]), "r"((a)[1]), "r"((a)[2]), "r"((a)[3]), "r"(b0), "r"(b1))

#define LDM_X4(r0, r1, r2, r3, addr)                                            \
    asm volatile("ldmatrix.sync.aligned.m8n8.x4.shared.b16 {%0,%1,%2,%3}, [%4];" \
        : "=r"(r0), "=r"(r1), "=r"(r2), "=r"(r3) : "r"(addr))

__global__ __launch_bounds__(128, 2) void mlp_kernel(const float* __restrict__ Wd,
                                                     const float* __restrict__ Wm,
                                                     float* __restrict__ out) {
    __shared__ __align__(16) ull s_wdp[2][16][4];           // packed Wd pairs, 1 KB
    __shared__ __align__(16) uint32_t s_hb[2][64 * HBW];    // fp16 h, 18 KB
    __shared__ float s_obuf[C1 * 16];                       // 8 KB

    const int tid = threadIdx.x;
    const int w = tid >> 5, lane = tid & 31;
    const int q = lane & 3, nl = lane >> 2;
    const int g = blockIdx.x >> 3;
    const int m_base = (blockIdx.x & 7) * 16;

    // pack Wd: (half, j, comp) -> (Wd[c0][comp], Wd[c1][comp]), c0=32h+2j
    {
        const int h = tid >> 6, j = (tid >> 2) & 15, c = tid & 3;
        const int c0 = 32 * h + 2 * j;
        s_wdp[h][j][c] = packf(Wd[c0 * 4 + c], Wd[(c0 + 1) * 4 + c]);
    }

    // Wm -> exact fp16 hi/lo fragments in registers
    uint32_t Ah[2][4][4], Al[2][4][4];
#pragma unroll
    for (int rr = 0; rr < 4; ++rr) {
        const int r = 32 * w + 16 * (rr >> 1) + 8 * (rr & 1) + nl;
        const float* wr = Wm + (size_t)r * C0;
#pragma unroll
        for (int kt = 0; kt < 4; ++kt)
#pragma unroll
            for (int hf = 0; hf < 2; ++hf) {
                float2 v = *(const float2*)(wr + kt * 16 + 8 * hf + 2 * q);
                __half2 h2 = __floats2half2_rn(v.x, v.y);
                __half2 l2 = __floats2half2_rn(v.x - __low2float(h2),
                                               v.y - __high2float(h2));
                Ah[rr >> 1][kt][(rr & 1) + 2 * hf] = *(uint32_t*)&h2;
                Al[rr >> 1][kt][(rr & 1) + 2 * hf] = *(uint32_t*)&l2;
            }
    }
    __syncthreads();

    const int l1_a  = tid >> 6;
    const int l1_k  = (tid >> 1) & 31;
    const int l1_ch = tid & 1;
    const int prow  = l1_a * 32 + l1_k;

    const uint32_t hb0 = (uint32_t)__cvta_generic_to_shared(&s_hb[0][0]);
    const uint32_t laneoff = (uint32_t)((lane & 7) * (HBW * 4) + (lane >> 3) * 16);
    const uint32_t BUFB = 64 * HBW * 4;

    float fsum[2][2][2];
#pragma unroll
    for (int i = 0; i < 8; ++i) (&fsum[0][0][0])[i] = 0.f;

    for (int pair = 0; pair < 8; ++pair) {
        for (int dti = 0; dti < 3; ++dti) {
            const int t = pair * 3 + dti;
            const int buf = t & 1;
            // ---- produce layer-1 h (fp16) with packed fma2 ----
            {
                const int m = m_base + pair * 2 + l1_a;
                float4 dv = g_disp[((size_t)(dti * GROUPS + g) * MANCH + m) * KNBR + l1_k];
                const ull dvx2 = packf(dv.x, dv.x);
                const ull dvy2 = packf(dv.y, dv.y);
                const ull dvz2 = packf(dv.z, dv.z);
                const ull dvw2 = packf(dv.w, dv.w);
                uint32_t* hrow = &s_hb[buf][prow * HBW + l1_ch * 16];
                const ull* wp = &s_wdp[l1_ch][0][0];
#pragma unroll
                for (int j = 0; j < 16; ++j) {
                    ull acc = fma2(wp[4 * j + 0], dvx2, 0ull);
                    acc = fma2(wp[4 * j + 1], dvy2, acc);
                    acc = fma2(wp[4 * j + 2], dvz2, acc);
                    acc = fma2(wp[4 * j + 3], dvw2, acc);
                    float h0, h1;
                    unpackf(acc, h0, h1);
                    __half2 p = __floats2half2_rn(fmaxf(h0, 0.f), fmaxf(h1, 0.f));
                    hrow[j] = *(uint32_t*)&p;
                }
            }
            __syncthreads();

            // ---- consume: 2-pass MMA, nt processed in pairs ----
            float acc[2][8][4];
#pragma unroll
            for (int i = 0; i < 64; ++i) (&acc[0][0][0])[i] = 0.f;
            const uint32_t ab = hb0 + (uint32_t)buf * BUFB + laneoff;
#pragma unroll
            for (int ntp = 0; ntp < 4; ++ntp) {
                const int nt0 = 2 * ntp, nt1 = nt0 + 1;
                uint32_t b0[8], b1[8];
                const uint32_t r0 = (uint32_t)(nt0 * 8 * HBW * 4);
                const uint32_t r1 = (uint32_t)(nt1 * 8 * HBW * 4);
                LDM_X4(b0[0], b0[1], b0[2], b0[3], ab + r0);
                LDM_X4(b0[4], b0[5], b0[6], b0[7], ab + r0 + 64);
                LDM_X4(b1[0], b1[1], b1[2], b1[3], ab + r1);
                LDM_X4(b1[4], b1[5], b1[6], b1[7], ab + r1 + 64);
#pragma unroll
                for (int kt = 0; kt < 4; ++kt) {
#pragma unroll
                    for (int mt = 0; mt < 2; ++mt) {
                        MMA_F16(acc[mt][nt0], Ah[mt][kt], b0[2 * kt], b0[2 * kt + 1]);
                        MMA_F16(acc[mt][nt1], Ah[mt][kt], b1[2 * kt], b1[2 * kt + 1]);
                        MMA_F16(acc[mt][nt0], Al[mt][kt], b0[2 * kt], b0[2 * kt + 1]);
                        MMA_F16(acc[mt][nt1], Al[mt][kt], b1[2 * kt], b1[2 * kt + 1]);
                    }
                }
            }

            // ---- epilogue: max over k, relu, accumulate over dt ----
#pragma unroll
            for (int mt = 0; mt < 2; ++mt)
#pragma unroll
                for (int a = 0; a < 2; ++a) {
                    float m0 = -1e30f, m1 = -1e30f;
#pragma unroll
                    for (int nt = a * 4; nt < a * 4 + 4; ++nt) {
                        m0 = fmaxf(m0, fmaxf(acc[mt][nt][0], acc[mt][nt][1]));
                        m1 = fmaxf(m1, fmaxf(acc[mt][nt][2], acc[mt][nt][3]));
                    }
                    m0 = fmaxf(m0, __shfl_xor_sync(0xffffffffu, m0, 1));
                    m0 = fmaxf(m0, __shfl_xor_sync(0xffffffffu, m0, 2));
                    m1 = fmaxf(m1, __shfl_xor_sync(0xffffffffu, m1, 1));
                    m1 = fmaxf(m1, __shfl_xor_sync(0xffffffffu, m1, 2));
                    fsum[mt][0][a] += fmaxf(m0, 0.f);
                    fsum[mt][1][a] += fmaxf(m1, 0.f);
                }
        }
        if (q == 0) {
#pragma unroll
            for (int mt = 0; mt < 2; ++mt)
#pragma unroll
                for (int rh = 0; rh < 2; ++rh)
#pragma unroll
                    for (int a = 0; a < 2; ++a) {
                        int o = 32 * w + 16 * mt + 8 * rh + nl;
                        s_obuf[o * 16 + pair * 2 + a] = fsum[mt][rh][a];
                    }
        }
#pragma unroll
        for (int i = 0; i < 8; ++i) (&fsum[0][0][0])[i] = 0.f;
    }
    __syncthreads();

    float4* dst = (float4*)(out + 24576 + ((size_t)g * C1 + tid) * MANCH + m_base);
    const float4* src = (const float4*)(s_obuf + tid * 16);
#pragma unroll
    for (int i = 0; i < 4; ++i) dst[i] = src[i];
}

// ---------------------------------------------------------------------------
extern "C" void kernel_launch(void* const* d_in, const int* in_sizes, int n_in,
                              void* d_out, int out_size) {
    const float* xyzs = (const float*)d_in[0];
    const float* Wd   = (const float*)d_in[1];
    const float* Wm   = (const float*)d_in[2];
    float* out = (float*)d_out;

    fps_kernel<<<GROUPS, 256>>>(xyzs, out);
    ball_kernel<<<GROUPS * 3, 256>>>(xyzs, out);
    mlp_kernel<<<GROUPS * 8, 128>>>(Wd, Wm, out);
}

// round 9
// speedup vs baseline: 2.6651x; 1.1271x over previous
#include <cuda_runtime.h>
#include <cuda_bf16.h>
#include <cuda_fp16.h>
#include <cstdint>

#define BATCH   4
#define TFRAMES 32
#define NPTS    4096
#define FOUT    16
#define GROUPS  64
#define MANCH   128
#define KNBR    32
#define C0      64
#define C1      128

__device__ float4 g_disp[3 * GROUPS * MANCH * KNBR];   // 12.58 MB scratch

typedef unsigned long long ull;

__device__ __forceinline__ ull fma2(ull a, ull b, ull c) {
    ull d;
    asm("fma.rn.f32x2 %0, %1, %2, %3;" : "=l"(d) : "l"(a), "l"(b), "l"(c));
    return d;
}
__device__ __forceinline__ ull packf(float lo, float hi) {
    ull r;
    asm("mov.b64 %0, {%1, %2};" : "=l"(r) : "f"(lo), "f"(hi));
    return r;
}
__device__ __forceinline__ void unpackf(ull v, float& lo, float& hi) {
    asm("mov.b64 {%0, %1}, %2;" : "=f"(lo), "=f"(hi) : "l"(v));
}

// ---------------------------------------------------------------------------
// Kernel 1: FPS. 128 threads (4 warps), 32 pts/thread in registers.
// Short cross-warp combine: 4 smem keys, parity double-buffered, 1 barrier.
// ---------------------------------------------------------------------------
__global__ __launch_bounds__(128) void fps_kernel(const float* __restrict__ xyzs,
                                                  float* __restrict__ out_xyz) {
    const int g = blockIdx.x;
    const int b = g >> 4, f = g & 15;
    const float* fr = xyzs + ((size_t)(b * TFRAMES + 2 * f) * NPTS) * 3;
    const int tid = threadIdx.x;
    const int wid = tid >> 5, lane = tid & 31;

    __shared__ float sp[NPTS * 3];                 // 48 KB
    __shared__ ull wkey[2][4];
    for (int i = tid; i < NPTS * 3; i += 128) sp[i] = fr[i];
    __syncthreads();

    const ull ONE2 = packf(1.0f, 1.0f);
    ull px2[16], py2[16], pz2[16];
    float dist[32];
#pragma unroll
    for (int j = 0; j < 16; ++j) {
        int p0 = j * 256 + tid, p1 = p0 + 128;
        px2[j] = packf(sp[p0 * 3 + 0], sp[p1 * 3 + 0]);
        py2[j] = packf(sp[p0 * 3 + 1], sp[p1 * 3 + 1]);
        pz2[j] = packf(sp[p0 * 3 + 2], sp[p1 * 3 + 2]);
        dist[2 * j] = 1e10f; dist[2 * j + 1] = 1e10f;
    }

    float cx = sp[0], cy = sp[1], cz = sp[2];
    if (tid == 0) {
        float* o = out_xyz + (size_t)g * MANCH * 3;
        o[0] = cx; o[1] = cy; o[2] = cz;
    }

    for (int s = 1; s < MANCH; ++s) {
        const ull ncx2 = packf(-cx, -cx);
        const ull ncy2 = packf(-cy, -cy);
        const ull ncz2 = packf(-cz, -cz);
#pragma unroll
        for (int j = 0; j < 16; ++j) {
            ull ax = fma2(px2[j], ONE2, ncx2);
            ull ay = fma2(py2[j], ONE2, ncy2);
            ull az = fma2(pz2[j], ONE2, ncz2);
            ull mx = fma2(ax, ax, 0ull);
            ull my = fma2(ay, ay, 0ull);
            ull s1 = fma2(mx, ONE2, my);
            ull mz = fma2(az, az, 0ull);
            ull d2 = fma2(s1, ONE2, mz);
            float dlo, dhi;
            unpackf(d2, dlo, dhi);
            dist[2 * j]     = fminf(dist[2 * j], dlo);
            dist[2 * j + 1] = fminf(dist[2 * j + 1], dhi);
        }
        // tree max over 32 slots
        float t[16];
#pragma unroll
        for (int i = 0; i < 16; ++i) t[i] = fmaxf(dist[2 * i], dist[2 * i + 1]);
#pragma unroll
        for (int st = 8; st; st >>= 1)
#pragma unroll
            for (int i = 0; i < 8; ++i)
                if (i < st) t[i] = fmaxf(t[i], t[i + st]);
        unsigned wmax = __reduce_max_sync(0xffffffffu, __float_as_uint(t[0]));
        float wvf = __uint_as_float(wmax);
        unsigned cand = 0xffffffffu;
#pragma unroll
        for (int sl = 0; sl < 32; ++sl) {
            unsigned gi = (sl >> 1) * 256 + (sl & 1) * 128 + tid;
            if (dist[sl] == wvf) cand = min(cand, gi);
        }
        cand = __reduce_min_sync(0xffffffffu, cand);
        if (lane == 0)
            wkey[s & 1][wid] = ((ull)wmax << 32) | (unsigned)(~cand);
        __syncthreads();
        const ull* kk = wkey[s & 1];
        ull best = max(max(kk[0], kk[1]), max(kk[2], kk[3]));
        int wi = (int)(~(unsigned)best);
        cx = sp[wi * 3 + 0]; cy = sp[wi * 3 + 1]; cz = sp[wi * 3 + 2];
        if (tid == 0) {
            float* o = out_xyz + ((size_t)g * MANCH + s) * 3;
            o[0] = cx; o[1] = cy; o[2] = cz;
        }
    }
}

// ---------------------------------------------------------------------------
// Kernel 2: ball query (unchanged from R7; proven)
// ---------------------------------------------------------------------------
__global__ __launch_bounds__(256) void ball_kernel(const float* __restrict__ xyzs,
                                                   const float* __restrict__ anchors) {
    const int bid = blockIdx.x;
    const int g = bid / 3, dti = bid % 3;
    const int dt = dti - 1;
    const int b = g >> 4, f = g & 15;
    int t = 2 * f + dt;
    t = min(max(t, 0), TFRAMES - 1);
    const float* fr = xyzs + (size_t)(b * TFRAMES + t) * NPTS * 3;

    __shared__ float sx[NPTS], sy[NPTS], sz[NPTS];
    for (int p = threadIdx.x; p < NPTS; p += 256) {
        const float* pp = fr + p * 3;
        sx[p] = pp[0]; sy[p] = pp[1]; sz[p] = pp[2];
    }
    __syncthreads();

    const int w = threadIdx.x >> 5;
    const int lane = threadIdx.x & 31;
    const float r2 = (float)(0.15 * 0.15);
    const float tch = (float)dt;
    const ull ONE2 = packf(1.0f, 1.0f);
    const unsigned below = (1u << lane) - 1u;

    for (int m = w; m < MANCH; m += 8) {
        const float* a = anchors + ((size_t)g * MANCH + m) * 3;
        const float ax = a[0], ay = a[1], az = a[2];
        const ull nax2 = packf(-ax, -ax);
        const ull nay2 = packf(-ay, -ay);
        const ull naz2 = packf(-az, -az);
        float4* od = g_disp + ((size_t)(dti * GROUPS + g) * MANCH + m) * KNBR;

        int filled = 0;
        int firstidx = -1;

        for (int base = 0; base < NPTS; base += 128) {
            const int j0 = base + 4 * lane;
            float4 X = *(const float4*)(sx + j0);
            float4 Y = *(const float4*)(sy + j0);
            float4 Z = *(const float4*)(sz + j0);
            ull dxa = fma2(packf(X.x, X.y), ONE2, nax2);
            ull dxb = fma2(packf(X.z, X.w), ONE2, nax2);
            ull dya = fma2(packf(Y.x, Y.y), ONE2, nay2);
            ull dyb = fma2(packf(Y.z, Y.w), ONE2, nay2);
            ull dza = fma2(packf(Z.x, Z.y), ONE2, naz2);
            ull dzb = fma2(packf(Z.z, Z.w), ONE2, naz2);
            ull s1a = fma2(fma2(dxa, dxa, 0ull), ONE2, fma2(dya, dya, 0ull));
            ull s1b = fma2(fma2(dxb, dxb, 0ull), ONE2, fma2(dyb, dyb, 0ull));
            ull d2a = fma2(s1a, ONE2, fma2(dza, dza, 0ull));
            ull d2b = fma2(s1b, ONE2, fma2(dzb, dzb, 0ull));
            float d0, d1, d2, d3;
            unpackf(d2a, d0, d1);
            unpackf(d2b, d2, d3);
            bool p0 = d0 < r2, p1 = d1 < r2, p2 = d2 < r2, p3 = d3 < r2;
            unsigned m0 = __ballot_sync(0xffffffffu, p0);
            unsigned m1 = __ballot_sync(0xffffffffu, p1);
            unsigned m2 = __ballot_sync(0xffffffffu, p2);
            unsigned m3 = __ballot_sync(0xffffffffu, p3);
            unsigned anyh = m0 | m1 | m2 | m3;
            if (anyh) {
                int pos = filled + __popc(m0 & below) + __popc(m1 & below)
                                 + __popc(m2 & below) + __popc(m3 & below);
                float x0, x1, y0, y1, z0, z1, x2, x3, y2, y3, z2, z3;
                unpackf(dxa, x0, x1); unpackf(dya, y0, y1); unpackf(dza, z0, z1);
                unpackf(dxb, x2, x3); unpackf(dyb, y2, y3); unpackf(dzb, z2, z3);
                if (p0) { if (pos < KNBR) od[pos] = make_float4(x0, y0, z0, tch); pos++; }
                if (p1) { if (pos < KNBR) od[pos] = make_float4(x1, y1, z1, tch); pos++; }
                if (p2) { if (pos < KNBR) od[pos] = make_float4(x2, y2, z2, tch); pos++; }
                if (p3) { if (pos < KNBR) od[pos] = make_float4(x3, y3, z3, tch); pos++; }
                if (firstidx < 0) {
                    unsigned i0 = m0 ? 4u * (__ffs(m0) - 1)     : 0xffffu;
                    unsigned i1 = m1 ? 4u * (__ffs(m1) - 1) + 1 : 0xffffu;
                    unsigned i2 = m2 ? 4u * (__ffs(m2) - 1) + 2 : 0xffffu;
                    unsigned i3 = m3 ? 4u * (__ffs(m3) - 1) + 3 : 0xffffu;
                    firstidx = base + (int)min(min(i0, i1), min(i2, i3));
                }
                filled += __popc(m0) + __popc(m1) + __popc(m2) + __popc(m3);
                if (filled >= KNBR) break;
            }
        }
        if (filled < KNBR) {
            int fi = (firstidx < 0) ? 0 : firstidx;
            float fx = sx[fi] - ax, fy = sy[fi] - ay, fz = sz[fi] - az;
            int s = filled + lane;
            if (s < KNBR) od[s] = make_float4(fx, fy, fz, tch);
        }
    }
}

// ---------------------------------------------------------------------------
// Kernel 3: MLP. 3 dt-subtiles per phase: produce 3, ONE barrier, consume 3.
// 9 barriers total instead of 24. Dynamic smem h buffers (2 x 3 x 9 KB).
// ---------------------------------------------------------------------------
#define HBW 36
#define TILEW (64 * HBW)          // words per subtile
#define TILEB (TILEW * 4)         // 9216 bytes

#define MMA_F16(d, a, b0, b1)                                                   \
    asm("mma.sync.aligned.m16n8k16.row.col.f32.f16.f16.f32 "                    \
        "{%0,%1,%2,%3}, {%4,%5,%6,%7}, {%8,%9}, {%0,%1,%2,%3};"                 \
        : "+f"((d)[0]), "+f"((d)[1]), "+f"((d)[2]), "+f"((d)[3])                \
        : "r"((a)[0]), "r"((a)[1]), "r"((a)[2]), "r"((a)[3]), "r"(b0), "r"(b1))

#define LDM_X4(r0, r1, r2, r3, addr)                                            \
    asm volatile("ldmatrix.sync.aligned.m8n8.x4.shared.b16 {%0,%1,%2,%3}, [%4];" \
        : "=r"(r0), "=r"(r1), "=r"(r2), "=r"(r3) : "r"(addr))

__global__ __launch_bounds__(128, 2) void mlp_kernel(const float* __restrict__ Wd,
                                                     const float* __restrict__ Wm,
                                                     float* __restrict__ out) {
    extern __shared__ __align__(16) uint32_t s_hb[];        // [2][3][TILEW]
    __shared__ __align__(16) ull s_wdp[2][16][4];
    __shared__ float s_obuf[C1 * 16];

    const int tid = threadIdx.x;
    const int w = tid >> 5, lane = tid & 31;
    const int q = lane & 3, nl = lane >> 2;
    const int g = blockIdx.x >> 3;
    const int m_base = (blockIdx.x & 7) * 16;

    {
        const int h = tid >> 6, j = (tid >> 2) & 15, c = tid & 3;
        const int c0 = 32 * h + 2 * j;
        s_wdp[h][j][c] = packf(Wd[c0 * 4 + c], Wd[(c0 + 1) * 4 + c]);
    }

    uint32_t Ah[2][4][4], Al[2][4][4];
#pragma unroll
    for (int rr = 0; rr < 4; ++rr) {
        const int r = 32 * w + 16 * (rr >> 1) + 8 * (rr & 1) + nl;
        const float* wr = Wm + (size_t)r * C0;
#pragma unroll
        for (int kt = 0; kt < 4; ++kt)
#pragma unroll
            for (int hf = 0; hf < 2; ++hf) {
                float2 v = *(const float2*)(wr + kt * 16 + 8 * hf + 2 * q);
                __half2 h2 = __floats2half2_rn(v.x, v.y);
                __half2 l2 = __floats2half2_rn(v.x - __low2float(h2),
                                               v.y - __high2float(h2));
                Ah[rr >> 1][kt][(rr & 1) + 2 * hf] = *(uint32_t*)&h2;
                Al[rr >> 1][kt][(rr & 1) + 2 * hf] = *(uint32_t*)&l2;
            }
    }
    __syncthreads();

    const int l1_a  = tid >> 6;
    const int l1_k  = (tid >> 1) & 31;
    const int l1_ch = tid & 1;
    const int prow  = l1_a * 32 + l1_k;
    const ull* wp = &s_wdp[l1_ch][0][0];

    const uint32_t hb0 = (uint32_t)__cvta_generic_to_shared(&s_hb[0]);
    const uint32_t laneoff = (uint32_t)((lane & 7) * (HBW * 4) + (lane >> 3) * 16);

    // producer for one pair (3 subtiles) into buffer `buf`
    auto produce = [&](int pair, int buf) {
        const int m = m_base + pair * 2 + l1_a;
        float4 dv[3];
#pragma unroll
        for (int sub = 0; sub < 3; ++sub)
            dv[sub] = g_disp[((size_t)(sub * GROUPS + g) * MANCH + m) * KNBR + l1_k];
#pragma unroll
        for (int sub = 0; sub < 3; ++sub) {
            const ull dvx2 = packf(dv[sub].x, dv[sub].x);
            const ull dvy2 = packf(dv[sub].y, dv[sub].y);
            const ull dvz2 = packf(dv[sub].z, dv[sub].z);
            const ull dvw2 = packf(dv[sub].w, dv[sub].w);
            uint32_t* hrow = &s_hb[(buf * 3 + sub) * TILEW + prow * HBW + l1_ch * 16];
#pragma unroll
            for (int j = 0; j < 16; ++j) {
                ull acc = fma2(wp[4 * j + 0], dvx2, 0ull);
                acc = fma2(wp[4 * j + 1], dvy2, acc);
                acc = fma2(wp[4 * j + 2], dvz2, acc);
                acc = fma2(wp[4 * j + 3], dvw2, acc);
                float h0, h1;
                unpackf(acc, h0, h1);
                __half2 p = __floats2half2_rn(fmaxf(h0, 0.f), fmaxf(h1, 0.f));
                hrow[j] = *(uint32_t*)&p;
            }
        }
    };

    float fsum[2][2][2];
#pragma unroll
    for (int i = 0; i < 8; ++i) (&fsum[0][0][0])[i] = 0.f;

    produce(0, 0);
    __syncthreads();

    for (int pair = 0; pair < 8; ++pair) {
        const int buf = pair & 1;
#pragma unroll
        for (int sub = 0; sub < 3; ++sub) {
            float acc[2][8][4];
#pragma unroll
            for (int i = 0; i < 64; ++i) (&acc[0][0][0])[i] = 0.f;
            const uint32_t ab = hb0 + (uint32_t)(buf * 3 + sub) * TILEB + laneoff;
#pragma unroll
            for (int ntp = 0; ntp < 4; ++ntp) {
                const int nt0 = 2 * ntp, nt1 = nt0 + 1;
                uint32_t b0[8], b1[8];
                const uint32_t r0 = (uint32_t)(nt0 * 8 * HBW * 4);
                const uint32_t r1 = (uint32_t)(nt1 * 8 * HBW * 4);
                LDM_X4(b0[0], b0[1], b0[2], b0[3], ab + r0);
                LDM_X4(b0[4], b0[5], b0[6], b0[7], ab + r0 + 64);
                LDM_X4(b1[0], b1[1], b1[2], b1[3], ab + r1);
                LDM_X4(b1[4], b1[5], b1[6], b1[7], ab + r1 + 64);
#pragma unroll
                for (int kt = 0; kt < 4; ++kt) {
#pragma unroll
                    for (int mt = 0; mt < 2; ++mt) {
                        MMA_F16(acc[mt][nt0], Ah[mt][kt], b0[2 * kt], b0[2 * kt + 1]);
                        MMA_F16(acc[mt][nt1], Ah[mt][kt], b1[2 * kt], b1[2 * kt + 1]);
                        MMA_F16(acc[mt][nt0], Al[mt][kt], b0[2 * kt], b0[2 * kt + 1]);
                        MMA_F16(acc[mt][nt1], Al[mt][kt], b1[2 * kt], b1[2 * kt + 1]);
                    }
                }
            }
#pragma unroll
            for (int mt = 0; mt < 2; ++mt)
#pragma unroll
                for (int a = 0; a < 2; ++a) {
                    float m0 = -1e30f, m1 = -1e30f;
#pragma unroll
                    for (int nt = a * 4; nt < a * 4 + 4; ++nt) {
                        m0 = fmaxf(m0, fmaxf(acc[mt][nt][0], acc[mt][nt][1]));
                        m1 = fmaxf(m1, fmaxf(acc[mt][nt][2], acc[mt][nt][3]));
                    }
                    m0 = fmaxf(m0, __shfl_xor_sync(0xffffffffu, m0, 1));
                    m0 = fmaxf(m0, __shfl_xor_sync(0xffffffffu, m0, 2));
                    m1 = fmaxf(m1, __shfl_xor_sync(0xffffffffu, m1, 1));
                    m1 = fmaxf(m1, __shfl_xor_sync(0xffffffffu, m1, 2));
                    fsum[mt][0][a] += fmaxf(m0, 0.f);
                    fsum[mt][1][a] += fmaxf(m1, 0.f);
                }
        }
        if (pair < 7) produce(pair + 1, buf ^ 1);
        if (q == 0) {
#pragma unroll
            for (int mt = 0; mt < 2; ++mt)
#pragma unroll
                for (int rh = 0; rh < 2; ++rh)
#pragma unroll
                    for (int a = 0; a < 2; ++a) {
                        int o = 32 * w + 16 * mt + 8 * rh + nl;
                        s_obuf[o * 16 + pair * 2 + a] = fsum[mt][rh][a];
                    }
        }
#pragma unroll
        for (int i = 0; i < 8; ++i) (&fsum[0][0][0])[i] = 0.f;
        __syncthreads();
    }

    float4* dst = (float4*)(out + 24576 + ((size_t)g * C1 + tid) * MANCH + m_base);
    const float4* src = (const float4*)(s_obuf + tid * 16);
#pragma unroll
    for (int i = 0; i < 4; ++i) dst[i] = src[i];
}

// ---------------------------------------------------------------------------
extern "C" void kernel_launch(void* const* d_in, const int* in_sizes, int n_in,
                              void* d_out, int out_size) {
    const float* xyzs = (const float*)d_in[0];
    const float* Wd   = (const float*)d_in[1];
    const float* Wm   = (const float*)d_in[2];
    float* out = (float*)d_out;

    cudaFuncSetAttribute(mlp_kernel, cudaFuncAttributeMaxDynamicSharedMemorySize,
                         2 * 3 * TILEB);

    fps_kernel<<<GROUPS, 128>>>(xyzs, out);
    ball_kernel<<<GROUPS * 3, 256>>>(xyzs, out);
    mlp_kernel<<<GROUPS * 8, 128, 2 * 3 * TILEB>>>(Wd, Wm, out);
}